// round 2
// baseline (speedup 1.0000x reference)
#include <cuda_runtime.h>
#include <cstdint>
#include <cstddef>

// Problem constants
#define BB   32
#define TT   1500
#define DIMD 512
#define NQ   8
#define KK   2048
#define NN   (BB*TT)              // 48000 vectors
#define QOUT_ELEMS (BB*DIMD*TT)   // 24576000
#define IDX_OFF QOUT_ELEMS
#define LOSS_OFF (QOUT_ELEMS + BB*NQ*TT)

// dist kernel tiling
#define NV 64        // vectors per block
#define KC 32        // codewords per k-tile
#define CS_STRIDE 36 // padded cs row (floats), keeps 16B alignment + limits bank conflicts
#define DIST_BLOCKS (NN / NV)            // 750
#define SMEM_BYTES ((DIMD*NV + DIMD*CS_STRIDE) * 4)   // 200 KB

// Scratch (static device globals; no runtime allocation)
__device__ float  g_res[(size_t)NN * DIMD];   // residual, layout [b,d,t] (same as x)
__device__ float  g_sx[NN];                   // per-vector sum of squares
__device__ float  g_sc[NQ * KK];              // per-codeword sum of squares
__device__ int    g_idx[NN];                  // argmin per vector (current stage)
__device__ double g_partial[NQ * DIST_BLOCKS]; // per-block loss partials

// ---------------------------------------------------------------------------
// sum(cb*cb, axis=-1): scalar sequential fp32, mul then add (no FMA contraction)
__global__ void k_sc(const float* __restrict__ cb) {
    int i = blockIdx.x * blockDim.x + threadIdx.x;
    if (i >= NQ * KK) return;
    const float* row = cb + (size_t)i * DIMD;
    float acc = 0.f;
    for (int d = 0; d < DIMD; ++d)
        acc = __fadd_rn(acc, __fmul_rn(row[d], row[d]));
    g_sc[i] = acc;
}

// sum(x*x) per vector (residual layout [b,d,t]): scalar sequential fp32
__global__ void k_sx(const float* __restrict__ res) {
    int n = blockIdx.x * blockDim.x + threadIdx.x;
    if (n >= NN) return;
    int b = n / TT, t = n - b * TT;
    const float* p = res + (size_t)b * (DIMD * TT) + t;
    float acc = 0.f;
    for (int d = 0; d < DIMD; ++d) {
        float v = p[(size_t)d * TT];
        acc = __fadd_rn(acc, __fmul_rn(v, v));
    }
    g_sx[n] = acc;
}

// ---------------------------------------------------------------------------
// Distance + argmin kernel. Block: 256 threads, 64 vectors x all 2048 codewords.
// Each thread: 2 vectors x 4 codewords register tile; dot = ascending-d FMA chain.
// Cycle model: FMA-pipe-bound (32 cyc/d/block vs issue 20, LDS 17).
extern __shared__ float s_dyn[];

__global__ __launch_bounds__(256, 1)
void k_dist(const float* __restrict__ res, const float* __restrict__ cbq,
            int q, float* __restrict__ out) {
    float* xs = s_dyn;                 // [512][64]
    float* cs = s_dyn + DIMD * NV;     // [512][CS_STRIDE], cols 0..31 used
    int tid = threadIdx.x;
    int n0 = blockIdx.x * NV;

    // load x tile: xs[d][v] = res[b, d, t]
    for (int i = tid; i < NV * DIMD; i += 256) {
        int d = i >> 6;          // i / 64
        int v = i & 63;
        int n = n0 + v;
        int b = n / TT, t = n - b * TT;
        xs[d * NV + v] = res[(size_t)b * (DIMD * TT) + (size_t)d * TT + t];
    }

    int vt = tid & 31, kt = tid >> 5;   // warp = fixed kt -> cs reads broadcast
    int v0 = vt * 2, k0l = kt * 4;
    float sx0 = g_sx[n0 + v0];
    float sx1 = g_sx[n0 + v0 + 1];

    float mind0 = 3.4e38f, mind1 = 3.4e38f;
    int   mini0 = 0,       mini1 = 0;

    for (int ktile = 0; ktile < KK / KC; ++ktile) {
        int kbase = ktile * KC;
        __syncthreads();  // protect cs from previous tile (and xs on first iter)
        for (int i = tid; i < KC * DIMD; i += 256) {
            int kk = i >> 9;     // i / 512
            int d  = i & 511;
            cs[d * CS_STRIDE + kk] = cbq[(size_t)(kbase + kk) * DIMD + d];
        }
        __syncthreads();

        float a00 = 0.f, a01 = 0.f, a02 = 0.f, a03 = 0.f;
        float a10 = 0.f, a11 = 0.f, a12 = 0.f, a13 = 0.f;
#pragma unroll 4
        for (int d = 0; d < DIMD; ++d) {
            float2 xv = *(const float2*)&xs[d * NV + v0];
            float4 cv = *(const float4*)&cs[d * CS_STRIDE + k0l];
            a00 = fmaf(xv.x, cv.x, a00);
            a01 = fmaf(xv.x, cv.y, a01);
            a02 = fmaf(xv.x, cv.z, a02);
            a03 = fmaf(xv.x, cv.w, a03);
            a10 = fmaf(xv.y, cv.x, a10);
            a11 = fmaf(xv.y, cv.y, a11);
            a12 = fmaf(xv.y, cv.z, a12);
            a13 = fmaf(xv.y, cv.w, a13);
        }

        // finalize: dist = fl(fl(sx - fl(2*dot)) + sc), ascending k, strict <
        const float* scp = g_sc + q * KK + kbase + k0l;
        float sc0 = scp[0], sc1 = scp[1], sc2 = scp[2], sc3 = scp[3];
        int kg = kbase + k0l;
        {
            float d0 = __fadd_rn(__fadd_rn(sx0, -__fmul_rn(2.0f, a00)), sc0);
            float d1 = __fadd_rn(__fadd_rn(sx0, -__fmul_rn(2.0f, a01)), sc1);
            float d2 = __fadd_rn(__fadd_rn(sx0, -__fmul_rn(2.0f, a02)), sc2);
            float d3 = __fadd_rn(__fadd_rn(sx0, -__fmul_rn(2.0f, a03)), sc3);
            if (d0 < mind0) { mind0 = d0; mini0 = kg + 0; }
            if (d1 < mind0) { mind0 = d1; mini0 = kg + 1; }
            if (d2 < mind0) { mind0 = d2; mini0 = kg + 2; }
            if (d3 < mind0) { mind0 = d3; mini0 = kg + 3; }
        }
        {
            float d0 = __fadd_rn(__fadd_rn(sx1, -__fmul_rn(2.0f, a10)), sc0);
            float d1 = __fadd_rn(__fadd_rn(sx1, -__fmul_rn(2.0f, a11)), sc1);
            float d2 = __fadd_rn(__fadd_rn(sx1, -__fmul_rn(2.0f, a12)), sc2);
            float d3 = __fadd_rn(__fadd_rn(sx1, -__fmul_rn(2.0f, a13)), sc3);
            if (d0 < mind1) { mind1 = d0; mini1 = kg + 0; }
            if (d1 < mind1) { mind1 = d1; mini1 = kg + 1; }
            if (d2 < mind1) { mind1 = d2; mini1 = kg + 2; }
            if (d3 < mind1) { mind1 = d3; mini1 = kg + 3; }
        }
    }

    // cross-thread reduction over kt (ties -> lowest index = jnp.argmin semantics)
    __syncthreads();
    float* rmin = xs;                       // [64][8]
    int*   ridx = (int*)(xs + NV * 8);      // [64][8]
    rmin[v0 * 8 + kt] = mind0;       ridx[v0 * 8 + kt] = mini0;
    rmin[(v0 + 1) * 8 + kt] = mind1; ridx[(v0 + 1) * 8 + kt] = mini1;
    __syncthreads();
    if (tid < NV) {
        int v = tid;
        float bd = rmin[v * 8];
        int   bi = ridx[v * 8];
        for (int j = 1; j < 8; ++j) {
            float dj = rmin[v * 8 + j];
            int   ij = ridx[v * 8 + j];
            if (dj < bd || (dj == bd && ij < bi)) { bd = dj; bi = ij; }
        }
        int n = n0 + v;
        g_idx[n] = bi;
        int b = n / TT, t = n - b * TT;
        out[IDX_OFF + (size_t)b * (NQ * TT) + (size_t)q * TT + t] = (float)bi;
    }
}

// ---------------------------------------------------------------------------
// Update kernel: straight-through quantize, accumulate output, update residual,
// per-block deterministic loss partial. Block covers 64 vectors x 4 d-chunks.
__global__ __launch_bounds__(256)
void k_update(const float* __restrict__ res_in, const float* __restrict__ cbq,
              int q, float* __restrict__ out) {
    int tid = threadIdx.x;
    int nl = tid & 63, dc = tid >> 6;       // dc in 0..3
    int n = blockIdx.x * 64 + nl;
    int b = n / TT, t = n - b * TT;
    int k = g_idx[n];
    const float* crow = cbq + (size_t)k * DIMD;
    size_t base = (size_t)b * (DIMD * TT) + t;

    double lacc = 0.0;
    int d0 = dc * 128;
    for (int d = d0; d < d0 + 128; ++d) {
        size_t off = base + (size_t)d * TT;
        float r = res_in[off];
        float c = crow[d];
        float t1 = __fadd_rn(c, -r);        // quant - residual
        float qo = __fadd_rn(r, t1);        // straight-through q_out
        float qprev = (q == 0) ? 0.f : out[off];
        out[off]   = __fadd_rn(qprev, qo);  // quantized_out += q_out
        g_res[off] = __fadd_rn(r, -qo);     // residual -= q_out
        lacc += (double)t1 * (double)t1;
    }

    __shared__ double sred[256];
    sred[tid] = lacc;
    __syncthreads();
    for (int s = 128; s > 0; s >>= 1) {
        if (tid < s) sred[tid] += sred[tid + s];
        __syncthreads();
    }
    if (tid == 0) g_partial[q * DIST_BLOCKS + blockIdx.x] = sred[0];
}

// Final: total_loss = fp32 sum over stages of (stage_sum / count)
__global__ void k_final(float* __restrict__ out) {
    __shared__ float lq[NQ];
    int q = threadIdx.x;
    if (q < NQ) {
        double s = 0.0;
        for (int i = 0; i < DIST_BLOCKS; ++i) s += g_partial[q * DIST_BLOCKS + i];
        lq[q] = (float)(s / (double)QOUT_ELEMS);
    }
    __syncthreads();
    if (q == 0) {
        float tl = 0.f;
        for (int i = 0; i < NQ; ++i) tl = __fadd_rn(tl, lq[i]);
        out[LOSS_OFF] = tl;
    }
}

// ---------------------------------------------------------------------------
extern "C" void kernel_launch(void* const* d_in, const int* in_sizes, int n_in,
                              void* d_out, int out_size) {
    const float* x  = (const float*)d_in[0];
    const float* cb = (const float*)d_in[1];
    float* out = (float*)d_out;

    cudaFuncSetAttribute(k_dist, cudaFuncAttributeMaxDynamicSharedMemorySize,
                         SMEM_BYTES);

    void* resg_v = nullptr;
    cudaGetSymbolAddress(&resg_v, g_res);
    const float* resg = (const float*)resg_v;

    k_sc<<<(NQ * KK + 255) / 256, 256>>>(cb);

    const float* res = x;   // stage 0 reads x directly
    for (int q = 0; q < NQ; ++q) {
        const float* cbq = cb + (size_t)q * KK * DIMD;
        k_sx<<<(NN + 255) / 256, 256>>>(res);
        k_dist<<<DIST_BLOCKS, 256, SMEM_BYTES>>>(res, cbq, q, out);
        k_update<<<DIST_BLOCKS, 256>>>(res, cbq, q, out);
        res = resg;         // subsequent stages read updated residual
    }
    k_final<<<1, 32>>>(out);
}

// round 4
// speedup vs baseline: 1.0695x; 1.0695x over previous
#include <cuda_runtime.h>
#include <cstdint>
#include <cstddef>

// Problem constants
#define BB   32
#define TT   1500
#define DIMD 512
#define NQ   8
#define KK   2048
#define NN   (BB*TT)              // 48000 vectors
#define QOUT_ELEMS (BB*DIMD*TT)   // 24576000
#define IDX_OFF QOUT_ELEMS
#define LOSS_OFF (QOUT_ELEMS + BB*NQ*TT)

// dist kernel tiling
#define NV 64        // vectors per block
#define KC 32        // codewords per k-tile
#define CS_STRIDE 36 // padded cs row (floats): 16B-aligned float4 slots
#define DIST_BLOCKS (NN / NV)            // 750
#define SMEM_BYTES ((DIMD*NV + DIMD*CS_STRIDE) * 4)   // 200 KB dynamic

// Scratch (static device globals; no runtime allocation)
__device__ float  g_res[(size_t)NN * DIMD];    // residual, layout [b,d,t]
__device__ float  g_sc[NQ * KK];               // per-codeword sum of squares
__device__ double g_partial[NQ * DIST_BLOCKS]; // per-block loss partials

// ---------------------------------------------------------------------------
// sum(cb*cb, axis=-1): scalar sequential fp32, mul then add (no FMA contraction)
__global__ void k_sc(const float* __restrict__ cb) {
    int i = blockIdx.x * blockDim.x + threadIdx.x;
    if (i >= NQ * KK) return;
    const float* row = cb + (size_t)i * DIMD;
    float acc = 0.f;
    for (int d = 0; d < DIMD; ++d)
        acc = __fadd_rn(acc, __fmul_rn(row[d], row[d]));
    g_sc[i] = acc;
}

// ---------------------------------------------------------------------------
// Fused stage kernel: distances (f32x2 FFMA) + argmin + straight-through
// update + loss partial. Block: 256 threads, 64 vectors x 2048 codewords.
extern __shared__ float s_dyn[];

__global__ __launch_bounds__(256, 1)
void k_dist(const float* __restrict__ res, const float* __restrict__ cbq,
            int q, float* __restrict__ out) {
    float* xs = s_dyn;                 // [512][64]
    float* cs = s_dyn + DIMD * NV;     // [512][CS_STRIDE], cols 0..31 used
    __shared__ float  sxs[NV];
    __shared__ int    sidx[NV];
    __shared__ float  rmin[NV * 8];
    __shared__ int    ridx[NV * 8];
    __shared__ double sred[256];

    int tid = threadIdx.x;
    int n0 = blockIdx.x * NV;

    // load x tile: xs[d][v] = res[b, d, t]
    for (int i = tid; i < NV * DIMD; i += 256) {
        int d = i >> 6;          // i / 64
        int v = i & 63;
        int n = n0 + v;
        int b = n / TT, t = n - b * TT;
        xs[d * NV + v] = res[(size_t)b * (DIMD * TT) + (size_t)d * TT + t];
    }
    __syncthreads();

    // fused sum(x*x): scalar sequential fp32 per vector (bitwise = old k_sx)
    if (tid < NV) {
        float acc = 0.f;
        for (int d = 0; d < DIMD; ++d) {
            float v = xs[d * NV + tid];
            acc = __fadd_rn(acc, __fmul_rn(v, v));
        }
        sxs[tid] = acc;
    }
    __syncthreads();

    int vt = tid & 31, kt = tid >> 5;   // warp has fixed kt -> cs reads broadcast
    int v0 = vt * 2, k0l = kt * 4;
    float sx0 = sxs[v0];
    float sx1 = sxs[v0 + 1];

    float mind0 = 3.4e38f, mind1 = 3.4e38f;
    int   mini0 = 0,       mini1 = 0;

    for (int ktile = 0; ktile < KK / KC; ++ktile) {
        int kbase = ktile * KC;
        __syncthreads();  // protect cs from previous tile
        for (int i = tid; i < KC * DIMD; i += 256) {
            int kk = i >> 9;     // i / 512
            int d  = i & 511;
            cs[d * CS_STRIDE + kk] = cbq[(size_t)(kbase + kk) * DIMD + d];
        }
        __syncthreads();

        // packed accumulators: a0={(v0,k0),(v0,k1)} a1={(v0,k2),(v0,k3)}
        //                      a2={(v1,k0),(v1,k1)} a3={(v1,k2),(v1,k3)}
        // Each lane of fma.rn.f32x2 is an IEEE fp32 FMA; per-(v,k) chain over d
        // is identical to the scalar version -> bitwise-same dot products.
        unsigned long long a0 = 0ull, a1 = 0ull, a2 = 0ull, a3 = 0ull;
#pragma unroll 4
        for (int d = 0; d < DIMD; ++d) {
            float2 xv = *(const float2*)&xs[d * NV + v0];
            ulonglong2 cv = *(const ulonglong2*)&cs[d * CS_STRIDE + k0l];
            unsigned long long xx0, xx1;
            asm("mov.b64 %0, {%1, %1};" : "=l"(xx0) : "f"(xv.x));
            asm("mov.b64 %0, {%1, %1};" : "=l"(xx1) : "f"(xv.y));
            asm("fma.rn.f32x2 %0, %1, %2, %0;" : "+l"(a0) : "l"(xx0), "l"(cv.x));
            asm("fma.rn.f32x2 %0, %1, %2, %0;" : "+l"(a1) : "l"(xx0), "l"(cv.y));
            asm("fma.rn.f32x2 %0, %1, %2, %0;" : "+l"(a2) : "l"(xx1), "l"(cv.x));
            asm("fma.rn.f32x2 %0, %1, %2, %0;" : "+l"(a3) : "l"(xx1), "l"(cv.y));
        }
        float a00, a01, a02, a03, a10, a11, a12, a13;
        asm("mov.b64 {%0, %1}, %2;" : "=f"(a00), "=f"(a01) : "l"(a0));
        asm("mov.b64 {%0, %1}, %2;" : "=f"(a02), "=f"(a03) : "l"(a1));
        asm("mov.b64 {%0, %1}, %2;" : "=f"(a10), "=f"(a11) : "l"(a2));
        asm("mov.b64 {%0, %1}, %2;" : "=f"(a12), "=f"(a13) : "l"(a3));

        // finalize: dist = fl(fl(sx - fl(2*dot)) + sc), ascending k, strict <
        const float* scp = g_sc + q * KK + kbase + k0l;
        float sc0 = scp[0], sc1 = scp[1], sc2 = scp[2], sc3 = scp[3];
        int kg = kbase + k0l;
        {
            float d0 = __fadd_rn(__fadd_rn(sx0, -__fmul_rn(2.0f, a00)), sc0);
            float d1 = __fadd_rn(__fadd_rn(sx0, -__fmul_rn(2.0f, a01)), sc1);
            float d2 = __fadd_rn(__fadd_rn(sx0, -__fmul_rn(2.0f, a02)), sc2);
            float d3 = __fadd_rn(__fadd_rn(sx0, -__fmul_rn(2.0f, a03)), sc3);
            if (d0 < mind0) { mind0 = d0; mini0 = kg + 0; }
            if (d1 < mind0) { mind0 = d1; mini0 = kg + 1; }
            if (d2 < mind0) { mind0 = d2; mini0 = kg + 2; }
            if (d3 < mind0) { mind0 = d3; mini0 = kg + 3; }
        }
        {
            float d0 = __fadd_rn(__fadd_rn(sx1, -__fmul_rn(2.0f, a10)), sc0);
            float d1 = __fadd_rn(__fadd_rn(sx1, -__fmul_rn(2.0f, a11)), sc1);
            float d2 = __fadd_rn(__fadd_rn(sx1, -__fmul_rn(2.0f, a12)), sc2);
            float d3 = __fadd_rn(__fadd_rn(sx1, -__fmul_rn(2.0f, a13)), sc3);
            if (d0 < mind1) { mind1 = d0; mini1 = kg + 0; }
            if (d1 < mind1) { mind1 = d1; mini1 = kg + 1; }
            if (d2 < mind1) { mind1 = d2; mini1 = kg + 2; }
            if (d3 < mind1) { mind1 = d3; mini1 = kg + 3; }
        }
    }

    // cross-thread reduction over kt (ties -> lowest index = jnp.argmin)
    rmin[v0 * 8 + kt] = mind0;       ridx[v0 * 8 + kt] = mini0;
    rmin[(v0 + 1) * 8 + kt] = mind1; ridx[(v0 + 1) * 8 + kt] = mini1;
    __syncthreads();
    if (tid < NV) {
        int v = tid;
        float bd = rmin[v * 8];
        int   bi = ridx[v * 8];
        for (int j = 1; j < 8; ++j) {
            float dj = rmin[v * 8 + j];
            int   ij = ridx[v * 8 + j];
            if (dj < bd || (dj == bd && ij < bi)) { bd = dj; bi = ij; }
        }
        sidx[v] = bi;
        int n = n0 + v;
        int b = n / TT, t = n - b * TT;
        out[IDX_OFF + (size_t)b * (NQ * TT) + (size_t)q * TT + t] = (float)bi;
    }
    __syncthreads();

    // Fused update: residual already in xs (bitwise = old k_update which read
    // the same values from global). 64 vectors x 4 d-chunks of 128.
    {
        int nl = tid & 63, dc = tid >> 6;
        int n = n0 + nl;
        int b = n / TT, t = n - b * TT;
        int k = sidx[nl];
        const float* crow = cbq + (size_t)k * DIMD;
        size_t base = (size_t)b * (DIMD * TT) + t;

        double lacc = 0.0;
        int d0 = dc * 128;
        for (int d = d0; d < d0 + 128; ++d) {
            size_t off = base + (size_t)d * TT;
            float r = xs[d * NV + nl];          // residual value
            float c = crow[d];
            float t1 = __fadd_rn(c, -r);        // quant - residual
            float qo = __fadd_rn(r, t1);        // straight-through q_out
            float qprev = (q == 0) ? 0.f : out[off];
            out[off]   = __fadd_rn(qprev, qo);  // quantized_out += q_out
            g_res[off] = __fadd_rn(r, -qo);     // residual -= q_out
            lacc += (double)t1 * (double)t1;
        }

        sred[tid] = lacc;
        __syncthreads();
        for (int s = 128; s > 0; s >>= 1) {
            if (tid < s) sred[tid] += sred[tid + s];
            __syncthreads();
        }
        if (tid == 0) g_partial[q * DIST_BLOCKS + blockIdx.x] = sred[0];
    }
}

// Final: total_loss = fp32 sum over stages of (stage_sum / count)
__global__ void k_final(float* __restrict__ out) {
    __shared__ float lq[NQ];
    int q = threadIdx.x;
    if (q < NQ) {
        double s = 0.0;
        for (int i = 0; i < DIST_BLOCKS; ++i) s += g_partial[q * DIST_BLOCKS + i];
        lq[q] = (float)(s / (double)QOUT_ELEMS);
    }
    __syncthreads();
    if (q == 0) {
        float tl = 0.f;
        for (int i = 0; i < NQ; ++i) tl = __fadd_rn(tl, lq[i]);
        out[LOSS_OFF] = tl;
    }
}

// ---------------------------------------------------------------------------
extern "C" void kernel_launch(void* const* d_in, const int* in_sizes, int n_in,
                              void* d_out, int out_size) {
    const float* x  = (const float*)d_in[0];
    const float* cb = (const float*)d_in[1];
    float* out = (float*)d_out;

    cudaFuncSetAttribute(k_dist, cudaFuncAttributeMaxDynamicSharedMemorySize,
                         SMEM_BYTES);

    void* resg_v = nullptr;
    cudaGetSymbolAddress(&resg_v, g_res);
    const float* resg = (const float*)resg_v;

    k_sc<<<(NQ * KK + 255) / 256, 256>>>(cb);

    const float* res = x;   // stage 0 reads x directly
    for (int q = 0; q < NQ; ++q) {
        const float* cbq = cb + (size_t)q * KK * DIMD;
        k_dist<<<DIST_BLOCKS, 256, SMEM_BYTES>>>(res, cbq, q, out);
        res = resg;         // subsequent stages read updated residual
    }
    k_final<<<1, 32>>>(out);
}

// round 5
// speedup vs baseline: 1.5441x; 1.4438x over previous
#include <cuda_runtime.h>
#include <cstdint>
#include <cstddef>

// Problem constants
#define BB   32
#define TT   1500
#define DIMD 512
#define NQ   8
#define KK   2048
#define NN   (BB*TT)              // 48000 vectors
#define QOUT_ELEMS (BB*DIMD*TT)   // 24576000
#define IDX_OFF QOUT_ELEMS
#define LOSS_OFF (QOUT_ELEMS + BB*NQ*TT)

// k_dist tiling: 64 vectors x 64-codeword k-tiles, d chunked by 128.
#define NV 64
#define KC 64
#define DC 128
#define NCH (DIMD/DC)            // 4 d-chunks
#define KTILES (KK/KC)           // 32
#define CS_STRIDE 68             // padded cs row; (68*d+8*kt)*4 stays 16B aligned
#define XS_FLOATS (DC*NV)        // 8192
#define CS_FLOATS (DC*CS_STRIDE) // 8704
#define SMEM_BYTES ((XS_FLOATS + CS_FLOATS)*4)   // 67584 B -> 3 CTAs/SM
#define DIST_BLOCKS (NN / NV)    // 750

// Scratch (static device globals; no runtime allocation)
__device__ float  g_res[(size_t)NN * DIMD];    // residual, layout [b,d,t]
__device__ float  g_sx[NN];                    // per-vector sum of squares
__device__ float  g_sc[NQ * KK];               // per-codeword sum of squares
__device__ int    g_idx[NN];                   // argmin per vector (stage-local)
__device__ double g_partial[NQ * DIST_BLOCKS]; // per-block loss partials

// ---------------------------------------------------------------------------
// sum(cb*cb, axis=-1): scalar sequential fp32, mul then add (no FMA contraction)
__global__ void k_sc(const float* __restrict__ cb) {
    int i = blockIdx.x * blockDim.x + threadIdx.x;
    if (i >= NQ * KK) return;
    const float* row = cb + (size_t)i * DIMD;
    float acc = 0.f;
    for (int d = 0; d < DIMD; ++d)
        acc = __fadd_rn(acc, __fmul_rn(row[d], row[d]));
    g_sc[i] = acc;
}

// sum(x*x) per vector: scalar sequential fp32 (bitwise-proven order)
__global__ void k_sx(const float* __restrict__ res) {
    int n = blockIdx.x * blockDim.x + threadIdx.x;
    if (n >= NN) return;
    int b = n / TT, t = n - b * TT;
    const float* p = res + (size_t)b * (DIMD * TT) + t;
    float acc = 0.f;
    for (int d = 0; d < DIMD; ++d) {
        float v = p[(size_t)d * TT];
        acc = __fadd_rn(acc, __fmul_rn(v, v));
    }
    g_sx[n] = acc;
}

// ---------------------------------------------------------------------------
// Distance + argmin. 256 threads, 3 CTAs/SM. Thread tile: 2 vectors x 8
// codewords (f32x2 FMA, pairs over adjacent k -> identical per-(v,k) ascending-d
// FMA chains -> bitwise-same dots as the passing R2/R4 kernels).
__global__ __launch_bounds__(256, 3)
void k_dist(const float* __restrict__ res, const float* __restrict__ cbq,
            int q, float* __restrict__ out) {
    extern __shared__ float sm[];
    float* xs = sm;               // [DC][NV]
    float* cs = sm + XS_FLOATS;   // [DC][CS_STRIDE], cols 0..63 used
    __shared__ float rmin[NV * 8];
    __shared__ int   ridx[NV * 8];

    int tid = threadIdx.x;
    int n0 = blockIdx.x * NV;
    int vt = tid & 31, kt = tid >> 5;    // kt uniform within a warp -> cs broadcast
    int v0 = 2 * vt, k0l = 8 * kt;

    float sx0 = g_sx[n0 + v0];
    float sx1 = g_sx[n0 + v0 + 1];

    float mind0 = 3.4e38f, mind1 = 3.4e38f;
    int   mini0 = 0,       mini1 = 0;

    for (int ktile = 0; ktile < KTILES; ++ktile) {
        int kbase = ktile * KC;
        // accumulators: a[j]   = {(v0, k0l+2j), (v0, k0l+2j+1)}  j=0..3
        //               a[4+j] = {(v1, k0l+2j), (v1, k0l+2j+1)}
        unsigned long long a0=0, a1=0, a2=0, a3=0, a4=0, a5=0, a6=0, a7=0;

        for (int c = 0; c < NCH; ++c) {
            int dbase = c * DC;
            __syncthreads();   // all readers done with previous chunk
            // xs chunk: xs[dd*NV + v] = res[b, dbase+dd, t]  (coalesced on t)
            for (int i = tid; i < XS_FLOATS; i += 256) {
                int dd = i >> 6, v = i & 63;
                int n = n0 + v;
                int b = n / TT, t = n - b * TT;
                xs[i] = res[(size_t)b * (DIMD * TT) + (size_t)(dbase + dd) * TT + t];
            }
            // cs chunk (transposed): cs[dd*CS_STRIDE + kk] = cbq[kbase+kk, dbase+dd]
            for (int i = tid; i < KC * DC; i += 256) {
                int kk = i >> 7, dd = i & 127;
                cs[dd * CS_STRIDE + kk] = cbq[(size_t)(kbase + kk) * DIMD + dbase + dd];
            }
            __syncthreads();

#pragma unroll 4
            for (int dd = 0; dd < DC; ++dd) {
                float2 xv = *(const float2*)&xs[dd * NV + v0];
                ulonglong2 cA = *(const ulonglong2*)&cs[dd * CS_STRIDE + k0l];
                ulonglong2 cB = *(const ulonglong2*)&cs[dd * CS_STRIDE + k0l + 4];
                unsigned long long xx0, xx1;
                asm("mov.b64 %0, {%1, %1};" : "=l"(xx0) : "f"(xv.x));
                asm("mov.b64 %0, {%1, %1};" : "=l"(xx1) : "f"(xv.y));
                asm("fma.rn.f32x2 %0, %1, %2, %0;" : "+l"(a0) : "l"(xx0), "l"(cA.x));
                asm("fma.rn.f32x2 %0, %1, %2, %0;" : "+l"(a1) : "l"(xx0), "l"(cA.y));
                asm("fma.rn.f32x2 %0, %1, %2, %0;" : "+l"(a2) : "l"(xx0), "l"(cB.x));
                asm("fma.rn.f32x2 %0, %1, %2, %0;" : "+l"(a3) : "l"(xx0), "l"(cB.y));
                asm("fma.rn.f32x2 %0, %1, %2, %0;" : "+l"(a4) : "l"(xx1), "l"(cA.x));
                asm("fma.rn.f32x2 %0, %1, %2, %0;" : "+l"(a5) : "l"(xx1), "l"(cA.y));
                asm("fma.rn.f32x2 %0, %1, %2, %0;" : "+l"(a6) : "l"(xx1), "l"(cB.x));
                asm("fma.rn.f32x2 %0, %1, %2, %0;" : "+l"(a7) : "l"(xx1), "l"(cB.y));
            }
        }

        // unpack dots (v x 8 ks, ascending k within thread)
        float d0[8], d1[8];
        asm("mov.b64 {%0, %1}, %2;" : "=f"(d0[0]), "=f"(d0[1]) : "l"(a0));
        asm("mov.b64 {%0, %1}, %2;" : "=f"(d0[2]), "=f"(d0[3]) : "l"(a1));
        asm("mov.b64 {%0, %1}, %2;" : "=f"(d0[4]), "=f"(d0[5]) : "l"(a2));
        asm("mov.b64 {%0, %1}, %2;" : "=f"(d0[6]), "=f"(d0[7]) : "l"(a3));
        asm("mov.b64 {%0, %1}, %2;" : "=f"(d1[0]), "=f"(d1[1]) : "l"(a4));
        asm("mov.b64 {%0, %1}, %2;" : "=f"(d1[2]), "=f"(d1[3]) : "l"(a5));
        asm("mov.b64 {%0, %1}, %2;" : "=f"(d1[4]), "=f"(d1[5]) : "l"(a6));
        asm("mov.b64 {%0, %1}, %2;" : "=f"(d1[6]), "=f"(d1[7]) : "l"(a7));

        // finalize: dist = fl(fl(sx - fl(2*dot)) + sc), ascending k, strict <
        const float* scp = g_sc + q * KK + kbase + k0l;
#pragma unroll
        for (int j = 0; j < 8; ++j) {
            float sc = scp[j];
            int kg = kbase + k0l + j;
            float dj0 = __fadd_rn(__fadd_rn(sx0, -__fmul_rn(2.0f, d0[j])), sc);
            if (dj0 < mind0) { mind0 = dj0; mini0 = kg; }
            float dj1 = __fadd_rn(__fadd_rn(sx1, -__fmul_rn(2.0f, d1[j])), sc);
            if (dj1 < mind1) { mind1 = dj1; mini1 = kg; }
        }
    }

    // cross-thread reduction over kt (ties -> lowest index = jnp.argmin)
    __syncthreads();
    rmin[v0 * 8 + kt] = mind0;       ridx[v0 * 8 + kt] = mini0;
    rmin[(v0 + 1) * 8 + kt] = mind1; ridx[(v0 + 1) * 8 + kt] = mini1;
    __syncthreads();
    if (tid < NV) {
        int v = tid;
        float bd = rmin[v * 8];
        int   bi = ridx[v * 8];
        for (int j = 1; j < 8; ++j) {
            float dj = rmin[v * 8 + j];
            int   ij = ridx[v * 8 + j];
            if (dj < bd || (dj == bd && ij < bi)) { bd = dj; bi = ij; }
        }
        int n = n0 + v;
        g_idx[n] = bi;
        int b = n / TT, t = n - b * TT;
        out[IDX_OFF + (size_t)b * (NQ * TT) + (size_t)q * TT + t] = (float)bi;
    }
}

// ---------------------------------------------------------------------------
// Update kernel (bitwise-proven R2 version): straight-through quantize,
// accumulate output, update residual, per-block loss partial.
__global__ __launch_bounds__(256)
void k_update(const float* __restrict__ res_in, const float* __restrict__ cbq,
              int q, float* __restrict__ out) {
    int tid = threadIdx.x;
    int nl = tid & 63, dc = tid >> 6;       // dc in 0..3
    int n = blockIdx.x * 64 + nl;
    int b = n / TT, t = n - b * TT;
    int k = g_idx[n];
    const float* crow = cbq + (size_t)k * DIMD;
    size_t base = (size_t)b * (DIMD * TT) + t;

    double lacc = 0.0;
    int d0 = dc * 128;
    for (int d = d0; d < d0 + 128; ++d) {
        size_t off = base + (size_t)d * TT;
        float r = res_in[off];
        float c = crow[d];
        float t1 = __fadd_rn(c, -r);        // quant - residual
        float qo = __fadd_rn(r, t1);        // straight-through q_out
        float qprev = (q == 0) ? 0.f : out[off];
        out[off]   = __fadd_rn(qprev, qo);  // quantized_out += q_out
        g_res[off] = __fadd_rn(r, -qo);     // residual -= q_out
        lacc += (double)t1 * (double)t1;
    }

    __shared__ double sred[256];
    sred[tid] = lacc;
    __syncthreads();
    for (int s = 128; s > 0; s >>= 1) {
        if (tid < s) sred[tid] += sred[tid + s];
        __syncthreads();
    }
    if (tid == 0) g_partial[q * DIST_BLOCKS + blockIdx.x] = sred[0];
}

// Final: total_loss = fp32 sum over stages of (stage_sum / count)
__global__ void k_final(float* __restrict__ out) {
    __shared__ float lq[NQ];
    int q = threadIdx.x;
    if (q < NQ) {
        double s = 0.0;
        for (int i = 0; i < DIST_BLOCKS; ++i) s += g_partial[q * DIST_BLOCKS + i];
        lq[q] = (float)(s / (double)QOUT_ELEMS);
    }
    __syncthreads();
    if (q == 0) {
        float tl = 0.f;
        for (int i = 0; i < NQ; ++i) tl = __fadd_rn(tl, lq[i]);
        out[LOSS_OFF] = tl;
    }
}

// ---------------------------------------------------------------------------
extern "C" void kernel_launch(void* const* d_in, const int* in_sizes, int n_in,
                              void* d_out, int out_size) {
    const float* x  = (const float*)d_in[0];
    const float* cb = (const float*)d_in[1];
    float* out = (float*)d_out;

    cudaFuncSetAttribute(k_dist, cudaFuncAttributeMaxDynamicSharedMemorySize,
                         SMEM_BYTES);

    void* resg_v = nullptr;
    cudaGetSymbolAddress(&resg_v, g_res);
    const float* resg = (const float*)resg_v;

    k_sc<<<(NQ * KK + 255) / 256, 256>>>(cb);

    const float* res = x;   // stage 0 reads x directly
    for (int q = 0; q < NQ; ++q) {
        const float* cbq = cb + (size_t)q * KK * DIMD;
        k_sx<<<(NN + 255) / 256, 256>>>(res);
        k_dist<<<DIST_BLOCKS, 256, SMEM_BYTES>>>(res, cbq, q, out);
        k_update<<<DIST_BLOCKS, 256>>>(res, cbq, q, out);
        res = resg;         // subsequent stages read updated residual
    }
    k_final<<<1, 32>>>(out);
}

// round 7
// speedup vs baseline: 3.8852x; 2.5162x over previous
#include <cuda_runtime.h>
#include <cuda_bf16.h>
#include <cstdint>
#include <cstddef>

// Problem constants
#define BB   32
#define TT   1500
#define DIMD 512
#define NQ   8
#define KK   2048
#define NN   (BB*TT)              // 48000 vectors
#define QOUT_ELEMS (BB*DIMD*TT)   // 24576000
#define IDX_OFF QOUT_ELEMS
#define LOSS_OFF (QOUT_ELEMS + BB*NQ*TT)

#define CAP     16                // max candidates kept per vector
#define MARGIN  1e-3f             // ~28 sigma of bf16-rounding dist error
#define UPD_BLOCKS (NN/64)        // 750

// GEMM tiling (mma.sync m16n8k16 bf16 — baseline PTX, valid on sm_100)
#define GM 128
#define GN 128
#define GKC 64
#define NKCH (DIMD/GKC)           // 8
#define MT (NN/GM)                // 375
#define NT (KK/GN)                // 16

// Scratch (static device globals; no runtime allocation)
__device__ float          g_res[(size_t)NN * DIMD];      // residual [b,d,t]
__device__ float          g_sx[NN];                      // exact row sums
__device__ float          g_sc[NQ * KK];                 // exact codeword sums
__device__ __nv_bfloat16  g_xb[(size_t)NN * DIMD];       // bf16 residual [vec][d]
__device__ __nv_bfloat16  g_cbb[(size_t)NQ * KK * DIMD]; // bf16 codebooks [k][d]
__device__ float          g_D[(size_t)NN * KK];          // approx scores
__device__ int            g_cand[NN * CAP];
__device__ int            g_cnt[NN];
__device__ int            g_idx[NN];
__device__ double         g_partial[NQ * UPD_BLOCKS];

#define SWZ128(o) ((o) ^ (((o) >> 3) & 0x70))

__device__ __forceinline__ uint32_t smem_u32(const void* p) {
    uint32_t a;
    asm("{ .reg .u64 t; cvta.to.shared.u64 t, %1; cvt.u32.u64 %0, t; }"
        : "=r"(a) : "l"(p));
    return a;
}

__device__ __forceinline__ void ldm_x4(uint32_t* r, uint32_t addr) {
    asm volatile("ldmatrix.sync.aligned.m8n8.x4.shared.b16 {%0,%1,%2,%3}, [%4];"
                 : "=r"(r[0]), "=r"(r[1]), "=r"(r[2]), "=r"(r[3]) : "r"(addr));
}

__device__ __forceinline__ void mma_bf16(float* c, const uint32_t* a,
                                         const uint32_t* b) {
    asm volatile(
        "mma.sync.aligned.m16n8k16.row.col.f32.bf16.bf16.f32 "
        "{%0,%1,%2,%3}, {%4,%5,%6,%7}, {%8,%9}, {%0,%1,%2,%3};"
        : "+f"(c[0]), "+f"(c[1]), "+f"(c[2]), "+f"(c[3])
        : "r"(a[0]), "r"(a[1]), "r"(a[2]), "r"(a[3]), "r"(b[0]), "r"(b[1]));
}

// ---------------------------------------------------------------------------
// Exact precompute kernels (bitwise-proven arithmetic orders)
__global__ void k_sc(const float* __restrict__ cb) {
    int i = blockIdx.x * blockDim.x + threadIdx.x;
    if (i >= NQ * KK) return;
    const float* row = cb + (size_t)i * DIMD;
    float acc = 0.f;
    for (int d = 0; d < DIMD; ++d)
        acc = __fadd_rn(acc, __fmul_rn(row[d], row[d]));
    g_sc[i] = acc;
}

__global__ void k_cbb(const float* __restrict__ cb) {
    size_t i = (size_t)blockIdx.x * blockDim.x + threadIdx.x;
    if (i >= (size_t)NQ * KK * DIMD) return;
    g_cbb[i] = __float2bfloat16(cb[i]);
}

// exact sum(x*x) (proven order) + bf16 conversion of residual into [vec][d]
__global__ void k_sx_xb(const float* __restrict__ res) {
    int n = blockIdx.x * blockDim.x + threadIdx.x;
    if (n >= NN) return;
    int b = n / TT, t = n - b * TT;
    const float* p = res + (size_t)b * (DIMD * TT) + t;
    __nv_bfloat16* xb = g_xb + (size_t)n * DIMD;
    float acc = 0.f;
    for (int d = 0; d < DIMD; ++d) {
        float v = p[(size_t)d * TT];
        acc = __fadd_rn(acc, __fmul_rn(v, v));
        xb[d] = __float2bfloat16(v);
    }
    g_sx[n] = acc;
}

// ---------------------------------------------------------------------------
// Approx score GEMM: D[vec][k] = sc[k] - 2 * dot_bf16(x_vec, c_k)
// CTA 128x128, 8 warps of 64x32, K chunked by 64. mma.sync m16n8k16 bf16.
__global__ __launch_bounds__(256, 2)
void k_gemm(int q) {
    __shared__ __align__(16) char smA[GM * 128];   // 128 rows x 64 bf16 (swz)
    __shared__ __align__(16) char smB[GN * 128];

    int tid = threadIdx.x;
    int wid = tid >> 5, lane = tid & 31;
    int wm = (wid & 1) * 64;          // warp m offset (2 warps over M)
    int wn = (wid >> 1) * 32;         // warp n offset (4 warps over N)
    int n0m = blockIdx.x * GM;
    int k0n = blockIdx.y * GN;

    const __nv_bfloat16* cbb = g_cbb + (size_t)q * KK * DIMD;
    uint32_t sa = smem_u32(smA), sb = smem_u32(smB);

    float acc[4][4][4];               // [m-tile][n-tile][frag]
#pragma unroll
    for (int i = 0; i < 4; ++i)
#pragma unroll
        for (int j = 0; j < 4; ++j)
#pragma unroll
            for (int f = 0; f < 4; ++f) acc[i][j][f] = 0.f;

    // ldmatrix lane addressing (byte offsets within tile, pre-swizzle):
    // A x4: lanes 0-15 -> row m0+lane, k-half 0; 16-31 -> row m0+lane-16, k-half 1
    int aRow = lane & 15, aHalf = (lane >> 4) & 1;
    // B x4 (two 8-wide n-tiles): 0-7 n-row, k0 | 8-15 n-row, k8 | 16-23 n+8, k0 | 24-31 n+8, k8
    int bRow = (lane & 7) + ((lane >> 4) << 3);
    int bHalf = (lane >> 3) & 1;

    for (int c = 0; c < NKCH; ++c) {
        int kb = c * GKC;
        __syncthreads();
        // fill A/B: 128 rows x 8 uint4 each; 4 uint4 per thread per tile
#pragma unroll
        for (int it = 0; it < 4; ++it) {
            int idx = it * 256 + tid;
            int r = idx >> 3, j = idx & 7;
            uint4 va = *(const uint4*)(g_xb + (size_t)(n0m + r) * DIMD + kb + j * 8);
            *(uint4*)(smA + SWZ128(r * 128 + j * 16)) = va;
            uint4 vb = *(const uint4*)(cbb + (size_t)(k0n + r) * DIMD + kb + j * 8);
            *(uint4*)(smB + SWZ128(r * 128 + j * 16)) = vb;
        }
        __syncthreads();

#pragma unroll
        for (int ks = 0; ks < 4; ++ks) {          // 4 x K=16 per chunk
            int kof = ks * 16;
            uint32_t af[4][4], bf[2][4];
#pragma unroll
            for (int i = 0; i < 4; ++i) {
                int row = wm + i * 16 + aRow;
                ldm_x4(af[i], sa + SWZ128(row * 128 + (kof + aHalf * 8) * 2));
            }
#pragma unroll
            for (int j = 0; j < 2; ++j) {
                int row = wn + j * 16 + bRow;
                ldm_x4(bf[j], sb + SWZ128(row * 128 + (kof + bHalf * 8) * 2));
            }
#pragma unroll
            for (int i = 0; i < 4; ++i) {
                mma_bf16(acc[i][0], af[i], &bf[0][0]);
                mma_bf16(acc[i][1], af[i], &bf[0][2]);
                mma_bf16(acc[i][2], af[i], &bf[1][0]);
                mma_bf16(acc[i][3], af[i], &bf[1][2]);
            }
        }
    }

    // epilogue: score = sc[k] - 2*dot; frag c0,c1 -> (m=lane/4, n=2*(lane%4)),
    // c2,c3 -> m+8. Write float2 pairs.
    const float* scp = g_sc + q * KK + k0n;
#pragma unroll
    for (int i = 0; i < 4; ++i) {
        int mrow = wm + i * 16 + (lane >> 2);
        size_t vrow0 = (size_t)(n0m + mrow) * KK + k0n;
        size_t vrow1 = (size_t)(n0m + mrow + 8) * KK + k0n;
#pragma unroll
        for (int j = 0; j < 4; ++j) {
            int nc = wn + j * 8 + 2 * (lane & 3);
            float2 p0, p1;
            p0.x = __fmaf_rn(-2.0f, acc[i][j][0], scp[nc]);
            p0.y = __fmaf_rn(-2.0f, acc[i][j][1], scp[nc + 1]);
            p1.x = __fmaf_rn(-2.0f, acc[i][j][2], scp[nc]);
            p1.y = __fmaf_rn(-2.0f, acc[i][j][3], scp[nc + 1]);
            *(float2*)(g_D + vrow0 + nc) = p0;
            *(float2*)(g_D + vrow1 + nc) = p1;
        }
    }
}

// ---------------------------------------------------------------------------
// Scan: per-vector warp finds min score + collects candidates (ascending k)
__global__ __launch_bounds__(256)
void k_scan() {
    int v = blockIdx.x * 8 + (threadIdx.x >> 5);
    int lane = threadIdx.x & 31;
    const float* row = g_D + (size_t)v * KK;

    float mn = 3.4e38f;
    for (int g = 0; g < KK / 32; ++g)
        mn = fminf(mn, row[g * 32 + lane]);
    for (int o = 16; o > 0; o >>= 1)
        mn = fminf(mn, __shfl_xor_sync(0xFFFFFFFFu, mn, o));
    float thr = mn + MARGIN;

    int total = 0;
    for (int g = 0; g < KK / 32; ++g) {
        float d = row[g * 32 + lane];
        unsigned bal = __ballot_sync(0xFFFFFFFFu, d <= thr);
        if (d <= thr) {
            int pos = total + __popc(bal & ((1u << lane) - 1u));
            if (pos < CAP) g_cand[v * CAP + pos] = g * 32 + lane;
        }
        total += __popc(bal);
    }
    if (lane == 0) g_cnt[v] = total;
}

// ---------------------------------------------------------------------------
// Exact argmin over candidates: bitwise-proven fp32 chain, strict <, asc k
__global__ __launch_bounds__(256)
void k_exact(const float* __restrict__ res, const float* __restrict__ cbq,
             int q, float* __restrict__ out) {
    int v = blockIdx.x * blockDim.x + threadIdx.x;
    if (v >= NN) return;
    int b = v / TT, t = v - b * TT;
    int cnt = g_cnt[v];
    int bi;
    if (cnt == 1) {
        bi = g_cand[v * CAP];       // unique candidate == exact argmin
    } else {
        const float* xp = res + (size_t)b * (DIMD * TT) + t;
        float sx = g_sx[v];
        float bd = 3.4e38f;
        bi = 0;
        int nc = (cnt > CAP) ? KK : cnt;   // overflow -> full exact scan
        for (int i = 0; i < nc; ++i) {
            int k = (cnt > CAP) ? i : g_cand[v * CAP + i];
            const float* crow = cbq + (size_t)k * DIMD;
            float dot = 0.f;
            for (int d = 0; d < DIMD; ++d)
                dot = __fmaf_rn(xp[(size_t)d * TT], crow[d], dot);
            float dist = __fadd_rn(__fadd_rn(sx, -__fmul_rn(2.0f, dot)),
                                   g_sc[q * KK + k]);
            if (dist < bd) { bd = dist; bi = k; }
        }
    }
    g_idx[v] = bi;
    out[IDX_OFF + (size_t)b * (NQ * TT) + (size_t)q * TT + t] = (float)bi;
}

// ---------------------------------------------------------------------------
// Update kernel (bitwise-proven): straight-through quantize, output accum,
// residual update, per-block loss partial.
__global__ __launch_bounds__(256)
void k_update(const float* __restrict__ res_in, const float* __restrict__ cbq,
              int q, float* __restrict__ out) {
    int tid = threadIdx.x;
    int nl = tid & 63, dc = tid >> 6;
    int n = blockIdx.x * 64 + nl;
    int b = n / TT, t = n - b * TT;
    int k = g_idx[n];
    const float* crow = cbq + (size_t)k * DIMD;
    size_t base = (size_t)b * (DIMD * TT) + t;

    double lacc = 0.0;
    int d0 = dc * 128;
    for (int d = d0; d < d0 + 128; ++d) {
        size_t off = base + (size_t)d * TT;
        float r = res_in[off];
        float c = crow[d];
        float t1 = __fadd_rn(c, -r);
        float qo = __fadd_rn(r, t1);
        float qprev = (q == 0) ? 0.f : out[off];
        out[off]   = __fadd_rn(qprev, qo);
        g_res[off] = __fadd_rn(r, -qo);
        lacc += (double)t1 * (double)t1;
    }

    __shared__ double sred[256];
    sred[tid] = lacc;
    __syncthreads();
    for (int s = 128; s > 0; s >>= 1) {
        if (tid < s) sred[tid] += sred[tid + s];
        __syncthreads();
    }
    if (tid == 0) g_partial[q * UPD_BLOCKS + blockIdx.x] = sred[0];
}

__global__ void k_final(float* __restrict__ out) {
    __shared__ float lq[NQ];
    int q = threadIdx.x;
    if (q < NQ) {
        double s = 0.0;
        for (int i = 0; i < UPD_BLOCKS; ++i) s += g_partial[q * UPD_BLOCKS + i];
        lq[q] = (float)(s / (double)QOUT_ELEMS);
    }
    __syncthreads();
    if (q == 0) {
        float tl = 0.f;
        for (int i = 0; i < NQ; ++i) tl = __fadd_rn(tl, lq[i]);
        out[LOSS_OFF] = tl;
    }
}

// ---------------------------------------------------------------------------
extern "C" void kernel_launch(void* const* d_in, const int* in_sizes, int n_in,
                              void* d_out, int out_size) {
    const float* x  = (const float*)d_in[0];
    const float* cb = (const float*)d_in[1];
    float* out = (float*)d_out;

    void* resg_v = nullptr;
    cudaGetSymbolAddress(&resg_v, g_res);
    const float* resg = (const float*)resg_v;

    k_sc<<<(NQ * KK + 255) / 256, 256>>>(cb);
    k_cbb<<<(int)(((size_t)NQ * KK * DIMD + 255) / 256), 256>>>(cb);

    const float* res = x;   // stage 0 reads x directly
    for (int q = 0; q < NQ; ++q) {
        const float* cbq = cb + (size_t)q * KK * DIMD;
        k_sx_xb<<<(NN + 255) / 256, 256>>>(res);
        dim3 gg(MT, NT);
        k_gemm<<<gg, 256>>>(q);
        k_scan<<<NN / 8, 256>>>();
        k_exact<<<(NN + 255) / 256, 256>>>(res, cbq, q, out);
        k_update<<<UPD_BLOCKS, 256>>>(res, cbq, q, out);
        res = resg;
    }
    k_final<<<1, 32>>>(out);
}

// round 11
// speedup vs baseline: 5.4122x; 1.3930x over previous
#include <cuda_runtime.h>
#include <cuda_bf16.h>
#include <cstdint>
#include <cstddef>

// Problem constants
#define BB   32
#define TT   1500
#define DIMD 512
#define NQ   8
#define KK   2048
#define NN   (BB*TT)              // 48000 vectors
#define QOUT_ELEMS (BB*DIMD*TT)   // 24576000
#define IDX_OFF QOUT_ELEMS
#define LOSS_OFF (QOUT_ELEMS + BB*NQ*TT)

#define CAP     16                // max candidates kept per vector
#define MARGIN  1e-3f             // ~28 sigma of bf16-rounding dist error
#define UPD_BLOCKS (NN/64)        // 750

// GEMM tiling (mma.sync m16n8k16 bf16 — baseline PTX, valid on sm_100)
#define GM 128
#define GN 128
#define GKC 64
#define NKCH (DIMD/GKC)           // 8
#define MT (NN/GM)                // 375
#define NT (KK/GN)                // 16
#define TILE_B (GM*128)           // 16384 bytes per tile buffer
#define GEMM_SMEM (4*TILE_B)      // 64 KB dynamic

// Scratch (static device globals; no runtime allocation)
__device__ float          g_res[(size_t)NN * DIMD];      // residual [b,d,t]
__device__ float          g_sx[NN];                      // exact row sums
__device__ float          g_sc[NQ * KK];                 // exact codeword sums
__device__ __nv_bfloat16  g_xb[(size_t)NN * DIMD];       // bf16 residual [vec][d]
__device__ __nv_bfloat16  g_cbb[(size_t)NQ * KK * DIMD]; // bf16 codebooks [k][d]
__device__ float          g_D[(size_t)NN * KK];          // approx scores
__device__ int            g_cand[NN * CAP];
__device__ int            g_cnt[NN];
__device__ int            g_idx[NN];
__device__ double         g_partial[NQ * UPD_BLOCKS];

#define SWZ128(o) ((o) ^ (((o) >> 3) & 0x70))

__device__ __forceinline__ uint32_t smem_u32(const void* p) {
    uint32_t a;
    asm("{ .reg .u64 t; cvta.to.shared.u64 t, %1; cvt.u32.u64 %0, t; }"
        : "=r"(a) : "l"(p));
    return a;
}

__device__ __forceinline__ void ldm_x4(uint32_t* r, uint32_t addr) {
    asm volatile("ldmatrix.sync.aligned.m8n8.x4.shared.b16 {%0,%1,%2,%3}, [%4];"
                 : "=r"(r[0]), "=r"(r[1]), "=r"(r[2]), "=r"(r[3]) : "r"(addr));
}

__device__ __forceinline__ void mma_bf16(float* c, const uint32_t* a,
                                         const uint32_t* b) {
    asm volatile(
        "mma.sync.aligned.m16n8k16.row.col.f32.bf16.bf16.f32 "
        "{%0,%1,%2,%3}, {%4,%5,%6,%7}, {%8,%9}, {%0,%1,%2,%3};"
        : "+f"(c[0]), "+f"(c[1]), "+f"(c[2]), "+f"(c[3])
        : "r"(a[0]), "r"(a[1]), "r"(a[2]), "r"(a[3]), "r"(b[0]), "r"(b[1]));
}

__device__ __forceinline__ void cpasync16(uint32_t dst, const void* src) {
    asm volatile("cp.async.cg.shared.global [%0], [%1], 16;"
                 :: "r"(dst), "l"(src) : "memory");
}
#define CP_COMMIT() asm volatile("cp.async.commit_group;" ::: "memory")

// ---------------------------------------------------------------------------
// Exact precompute kernels (bitwise-proven arithmetic orders)
__global__ void k_sc(const float* __restrict__ cb) {
    int i = blockIdx.x * blockDim.x + threadIdx.x;
    if (i >= NQ * KK) return;
    const float* row = cb + (size_t)i * DIMD;
    float acc = 0.f;
    for (int d = 0; d < DIMD; ++d)
        acc = __fadd_rn(acc, __fmul_rn(row[d], row[d]));
    g_sc[i] = acc;
}

__global__ void k_cbb(const float* __restrict__ cb) {
    size_t i = (size_t)blockIdx.x * blockDim.x + threadIdx.x;
    if (i >= (size_t)NQ * KK * DIMD) return;
    g_cbb[i] = __float2bfloat16(cb[i]);
}

// exact sum(x*x) (proven order) + bf16 conversion of residual into [vec][d]
__global__ void k_sx_xb(const float* __restrict__ res) {
    int n = blockIdx.x * blockDim.x + threadIdx.x;
    if (n >= NN) return;
    int b = n / TT, t = n - b * TT;
    const float* p = res + (size_t)b * (DIMD * TT) + t;
    __nv_bfloat16* xb = g_xb + (size_t)n * DIMD;
    float acc = 0.f;
    for (int d = 0; d < DIMD; ++d) {
        float v = p[(size_t)d * TT];
        acc = __fadd_rn(acc, __fmul_rn(v, v));
        xb[d] = __float2bfloat16(v);
    }
    g_sx[n] = acc;
}

// ---------------------------------------------------------------------------
// Approx score GEMM: D[vec][k] = sc[k] - 2 * dot_bf16(x_vec, c_k)
// CTA 128x128, 8 warps of 64x32, K in 8 chunks of 64, cp.async double-buffered.
// 64 KB dynamic smem arena: [A0 | A1 | B0 | B1], 16 KB each.
__global__ __launch_bounds__(256, 2)
void k_gemm(int q) {
    extern __shared__ __align__(1024) char smArena[];

    int tid = threadIdx.x;
    int wid = tid >> 5, lane = tid & 31;
    int wm = (wid & 1) * 64;          // warp m offset (2 warps over M)
    int wn = (wid >> 1) * 32;         // warp n offset (4 warps over N)
    int n0m = blockIdx.x * GM;
    int k0n = blockIdx.y * GN;

    const __nv_bfloat16* cbb = g_cbb + (size_t)q * KK * DIMD;
    uint32_t sbase = smem_u32(smArena);
    uint32_t sa[2] = { sbase,               sbase + TILE_B };
    uint32_t sb[2] = { sbase + 2 * TILE_B,  sbase + 3 * TILE_B };

    // per-thread fill coords: 1024 x 16B ops per tile, 4 per thread
    int fr[4], fj[4];
#pragma unroll
    for (int it = 0; it < 4; ++it) {
        int idx = it * 256 + tid;
        fr[it] = idx >> 3;            // row 0..127
        fj[it] = idx & 7;             // 16B column 0..7
    }

    auto fill = [&](int c, int buf) {
#pragma unroll
        for (int it = 0; it < 4; ++it) {
            int r = fr[it], j = fj[it];
            uint32_t soff = SWZ128(r * 128 + j * 16);
            cpasync16(sa[buf] + soff,
                      g_xb + (size_t)(n0m + r) * DIMD + c * GKC + j * 8);
            cpasync16(sb[buf] + soff,
                      cbb + (size_t)(k0n + r) * DIMD + c * GKC + j * 8);
        }
    };

    float acc[4][4][4];
#pragma unroll
    for (int i = 0; i < 4; ++i)
#pragma unroll
        for (int j = 0; j < 4; ++j)
#pragma unroll
            for (int f = 0; f < 4; ++f) acc[i][j][f] = 0.f;

    int aRow = lane & 15, aHalf = (lane >> 4) & 1;
    int bRow = (lane & 7) + ((lane >> 4) << 3);
    int bHalf = (lane >> 3) & 1;

    fill(0, 0);
    CP_COMMIT();

    for (int c = 0; c < NKCH; ++c) {
        int buf = c & 1;
        if (c < NKCH - 1) {
            fill(c + 1, buf ^ 1);
            CP_COMMIT();
            asm volatile("cp.async.wait_group 1;" ::: "memory");
        } else {
            asm volatile("cp.async.wait_group 0;" ::: "memory");
        }
        __syncthreads();          // buf c visible to all warps

#pragma unroll
        for (int ks = 0; ks < 4; ++ks) {
            int kof = ks * 16;
            uint32_t af[4][4], bf[2][4];
#pragma unroll
            for (int i = 0; i < 4; ++i) {
                int row = wm + i * 16 + aRow;
                ldm_x4(af[i], sa[buf] + SWZ128(row * 128 + (kof + aHalf * 8) * 2));
            }
#pragma unroll
            for (int j = 0; j < 2; ++j) {
                int row = wn + j * 16 + bRow;
                ldm_x4(bf[j], sb[buf] + SWZ128(row * 128 + (kof + bHalf * 8) * 2));
            }
#pragma unroll
            for (int i = 0; i < 4; ++i) {
                mma_bf16(acc[i][0], af[i], &bf[0][0]);
                mma_bf16(acc[i][1], af[i], &bf[0][2]);
                mma_bf16(acc[i][2], af[i], &bf[1][0]);
                mma_bf16(acc[i][3], af[i], &bf[1][2]);
            }
        }
        __syncthreads();          // all warps done with buf before refill
    }

    // epilogue: score = sc[k] - 2*dot
    const float* scp = g_sc + q * KK + k0n;
#pragma unroll
    for (int i = 0; i < 4; ++i) {
        int mrow = wm + i * 16 + (lane >> 2);
        size_t vrow0 = (size_t)(n0m + mrow) * KK + k0n;
        size_t vrow1 = (size_t)(n0m + mrow + 8) * KK + k0n;
#pragma unroll
        for (int j = 0; j < 4; ++j) {
            int nc = wn + j * 8 + 2 * (lane & 3);
            float2 p0, p1;
            p0.x = __fmaf_rn(-2.0f, acc[i][j][0], scp[nc]);
            p0.y = __fmaf_rn(-2.0f, acc[i][j][1], scp[nc + 1]);
            p1.x = __fmaf_rn(-2.0f, acc[i][j][2], scp[nc]);
            p1.y = __fmaf_rn(-2.0f, acc[i][j][3], scp[nc + 1]);
            *(float2*)(g_D + vrow0 + nc) = p0;
            *(float2*)(g_D + vrow1 + nc) = p1;
        }
    }
}

// ---------------------------------------------------------------------------
// Scan: per-vector warp finds min score + collects candidates (ascending k)
__global__ __launch_bounds__(256)
void k_scan() {
    int v = blockIdx.x * 8 + (threadIdx.x >> 5);
    int lane = threadIdx.x & 31;
    const float* row = g_D + (size_t)v * KK;

    float mn = 3.4e38f;
    for (int g = 0; g < KK / 32; ++g)
        mn = fminf(mn, row[g * 32 + lane]);
    for (int o = 16; o > 0; o >>= 1)
        mn = fminf(mn, __shfl_xor_sync(0xFFFFFFFFu, mn, o));
    float thr = mn + MARGIN;

    int total = 0;
    for (int g = 0; g < KK / 32; ++g) {
        float d = row[g * 32 + lane];
        unsigned bal = __ballot_sync(0xFFFFFFFFu, d <= thr);
        if (d <= thr) {
            int pos = total + __popc(bal & ((1u << lane) - 1u));
            if (pos < CAP) g_cand[v * CAP + pos] = g * 32 + lane;
        }
        total += __popc(bal);
    }
    if (lane == 0) g_cnt[v] = total;
}

// ---------------------------------------------------------------------------
// Exact argmin, warp-per-vector. Each lane computes ONE candidate's distance
// with the bitwise-proven sequential fp32 FMA chain; warp-reduce with exact
// comparisons, tie -> lowest index (== jnp.argmin over ascending k).
__global__ __launch_bounds__(256)
void k_exact(const float* __restrict__ res, const float* __restrict__ cbq,
             int q, float* __restrict__ out) {
    int v = blockIdx.x * 8 + (threadIdx.x >> 5);
    int lane = threadIdx.x & 31;
    if (v >= NN) return;
    int b = v / TT, t = v - b * TT;
    int cnt = g_cnt[v];
    int bi;
    if (cnt == 1) {
        bi = g_cand[v * CAP];       // unique candidate == exact argmin
    } else {
        const float* xp = res + (size_t)b * (DIMD * TT) + t;
        float sx = g_sx[v];
        const float* scq = g_sc + q * KK;
        float bd = 3.4e38f;
        int   bk = KK;              // sentinel (larger than any real index)
        if (cnt <= CAP) {
            if (lane < cnt) {
                int k = g_cand[v * CAP + lane];
                const float* crow = cbq + (size_t)k * DIMD;
                float dot = 0.f;
                for (int d = 0; d < DIMD; ++d)
                    dot = __fmaf_rn(xp[(size_t)d * TT], crow[d], dot);
                bd = __fadd_rn(__fadd_rn(sx, -__fmul_rn(2.0f, dot)), scq[k]);
                bk = k;
            }
        } else {
            // overflow: full exact scan, lane-strided (ascending k per lane)
            for (int k = lane; k < KK; k += 32) {
                const float* crow = cbq + (size_t)k * DIMD;
                float dot = 0.f;
                for (int d = 0; d < DIMD; ++d)
                    dot = __fmaf_rn(xp[(size_t)d * TT], crow[d], dot);
                float dist = __fadd_rn(__fadd_rn(sx, -__fmul_rn(2.0f, dot)),
                                       scq[k]);
                if (dist < bd) { bd = dist; bk = k; }
            }
        }
#pragma unroll
        for (int o = 16; o > 0; o >>= 1) {
            float od = __shfl_xor_sync(0xFFFFFFFFu, bd, o);
            int   ok = __shfl_xor_sync(0xFFFFFFFFu, bk, o);
            if (od < bd || (od == bd && ok < bk)) { bd = od; bk = ok; }
        }
        bi = bk;
    }
    if (lane == 0) {
        g_idx[v] = bi;
        out[IDX_OFF + (size_t)b * (NQ * TT) + (size_t)q * TT + t] = (float)bi;
    }
}

// ---------------------------------------------------------------------------
// Update kernel (bitwise-proven): straight-through quantize, output accum,
// residual update, per-block loss partial.
__global__ __launch_bounds__(256)
void k_update(const float* __restrict__ res_in, const float* __restrict__ cbq,
              int q, float* __restrict__ out) {
    int tid = threadIdx.x;
    int nl = tid & 63, dc = tid >> 6;
    int n = blockIdx.x * 64 + nl;
    int b = n / TT, t = n - b * TT;
    int k = g_idx[n];
    const float* crow = cbq + (size_t)k * DIMD;
    size_t base = (size_t)b * (DIMD * TT) + t;

    double lacc = 0.0;
    int d0 = dc * 128;
    for (int d = d0; d < d0 + 128; ++d) {
        size_t off = base + (size_t)d * TT;
        float r = res_in[off];
        float c = crow[d];
        float t1 = __fadd_rn(c, -r);
        float qo = __fadd_rn(r, t1);
        float qprev = (q == 0) ? 0.f : out[off];
        out[off]   = __fadd_rn(qprev, qo);
        g_res[off] = __fadd_rn(r, -qo);
        lacc += (double)t1 * (double)t1;
    }

    __shared__ double sred[256];
    sred[tid] = lacc;
    __syncthreads();
    for (int s = 128; s > 0; s >>= 1) {
        if (tid < s) sred[tid] += sred[tid + s];
        __syncthreads();
    }
    if (tid == 0) g_partial[q * UPD_BLOCKS + blockIdx.x] = sred[0];
}

__global__ void k_final(float* __restrict__ out) {
    __shared__ float lq[NQ];
    int q = threadIdx.x;
    if (q < NQ) {
        double s = 0.0;
        for (int i = 0; i < UPD_BLOCKS; ++i) s += g_partial[q * UPD_BLOCKS + i];
        lq[q] = (float)(s / (double)QOUT_ELEMS);
    }
    __syncthreads();
    if (q == 0) {
        float tl = 0.f;
        for (int i = 0; i < NQ; ++i) tl = __fadd_rn(tl, lq[i]);
        out[LOSS_OFF] = tl;
    }
}

// ---------------------------------------------------------------------------
extern "C" void kernel_launch(void* const* d_in, const int* in_sizes, int n_in,
                              void* d_out, int out_size) {
    const float* x  = (const float*)d_in[0];
    const float* cb = (const float*)d_in[1];
    float* out = (float*)d_out;

    void* resg_v = nullptr;
    cudaGetSymbolAddress(&resg_v, g_res);
    const float* resg = (const float*)resg_v;

    cudaFuncSetAttribute(k_gemm, cudaFuncAttributeMaxDynamicSharedMemorySize,
                         GEMM_SMEM);

    k_sc<<<(NQ * KK + 255) / 256, 256>>>(cb);
    k_cbb<<<(int)(((size_t)NQ * KK * DIMD + 255) / 256), 256>>>(cb);

    const float* res = x;   // stage 0 reads x directly
    for (int q = 0; q < NQ; ++q) {
        const float* cbq = cb + (size_t)q * KK * DIMD;
        k_sx_xb<<<(NN + 255) / 256, 256>>>(res);
        dim3 gg(MT, NT);
        k_gemm<<<gg, 256, GEMM_SMEM>>>(q);
        k_scan<<<NN / 8, 256>>>();
        k_exact<<<NN / 8, 256>>>(res, cbq, q, out);
        k_update<<<UPD_BLOCKS, 256>>>(res, cbq, q, out);
        res = resg;
    }
    k_final<<<1, 32>>>(out);
}

// round 12
// speedup vs baseline: 5.8672x; 1.0841x over previous
#include <cuda_runtime.h>
#include <cuda_bf16.h>
#include <cstdint>
#include <cstddef>

// Problem constants
#define BB   32
#define TT   1500
#define DIMD 512
#define NQ   8
#define KK   2048
#define NN   (BB*TT)              // 48000 vectors
#define QOUT_ELEMS (BB*DIMD*TT)   // 24576000
#define IDX_OFF QOUT_ELEMS
#define LOSS_OFF (QOUT_ELEMS + BB*NQ*TT)

#define CAP     16                // max candidates per vector for exact pass
#define TCAP    4                 // max candidates per (vector, n-tile)
#define MARGIN  1e-3f             // ~28 sigma of bf16-rounding dist error
#define UPD_BLOCKS (NN/64)        // 750

// GEMM tiling (mma.sync m16n8k16 bf16 — baseline PTX, valid on sm_100)
#define GM 128
#define GN 128
#define GKC 64
#define NKCH (DIMD/GKC)           // 8
#define MT (NN/GM)                // 375
#define NT (KK/GN)                // 16
#define TILE_B (GM*128)           // 16384 bytes per tile buffer
#define GEMM_SMEM (4*TILE_B)      // 64 KB dynamic

// Scratch (static device globals; no runtime allocation)
__device__ float          g_res[(size_t)NN * DIMD];      // residual [b,d,t]
__device__ float          g_sx[NN];                      // exact row sums
__device__ float          g_sc[NQ * KK];                 // exact codeword sums
__device__ __nv_bfloat16  g_xb[(size_t)NN * DIMD];       // bf16 residual [vec][d]
__device__ __nv_bfloat16  g_cbb[(size_t)NQ * KK * DIMD]; // bf16 codebooks [k][d]
// per-(vector, n-tile) summaries (replace the 393MB g_D score matrix)
__device__ float          g_tmin[NN * NT];
__device__ int            g_tcnt[NN * NT];
__device__ int            g_tck[NN * NT * TCAP];
__device__ float          g_tcs[NN * NT * TCAP];
__device__ int            g_cand[NN * CAP];
__device__ int            g_cnt[NN];
__device__ int            g_idx[NN];
__device__ double         g_partial[NQ * UPD_BLOCKS];

#define SWZ128(o) ((o) ^ (((o) >> 3) & 0x70))

__device__ __forceinline__ uint32_t smem_u32(const void* p) {
    uint32_t a;
    asm("{ .reg .u64 t; cvta.to.shared.u64 t, %1; cvt.u32.u64 %0, t; }"
        : "=r"(a) : "l"(p));
    return a;
}

// order-preserving float <-> uint for atomicMin
__device__ __forceinline__ unsigned fflip(float f) {
    unsigned u = __float_as_uint(f);
    return u ^ (unsigned)(((int)u >> 31) | 0x80000000);
}
__device__ __forceinline__ float funflip(unsigned u) {
    unsigned m = (u >> 31) ? 0x80000000u : 0xFFFFFFFFu;
    return __uint_as_float(u ^ m);
}

__device__ __forceinline__ void ldm_x4(uint32_t* r, uint32_t addr) {
    asm volatile("ldmatrix.sync.aligned.m8n8.x4.shared.b16 {%0,%1,%2,%3}, [%4];"
                 : "=r"(r[0]), "=r"(r[1]), "=r"(r[2]), "=r"(r[3]) : "r"(addr));
}

__device__ __forceinline__ void mma_bf16(float* c, const uint32_t* a,
                                         const uint32_t* b) {
    asm volatile(
        "mma.sync.aligned.m16n8k16.row.col.f32.bf16.bf16.f32 "
        "{%0,%1,%2,%3}, {%4,%5,%6,%7}, {%8,%9}, {%0,%1,%2,%3};"
        : "+f"(c[0]), "+f"(c[1]), "+f"(c[2]), "+f"(c[3])
        : "r"(a[0]), "r"(a[1]), "r"(a[2]), "r"(a[3]), "r"(b[0]), "r"(b[1]));
}

__device__ __forceinline__ void cpasync16(uint32_t dst, const void* src) {
    asm volatile("cp.async.cg.shared.global [%0], [%1], 16;"
                 :: "r"(dst), "l"(src) : "memory");
}
#define CP_COMMIT() asm volatile("cp.async.commit_group;" ::: "memory")

// ---------------------------------------------------------------------------
// Exact precompute kernels (bitwise-proven arithmetic orders)
__global__ void k_sc(const float* __restrict__ cb) {
    int i = blockIdx.x * blockDim.x + threadIdx.x;
    if (i >= NQ * KK) return;
    const float* row = cb + (size_t)i * DIMD;
    float acc = 0.f;
    for (int d = 0; d < DIMD; ++d)
        acc = __fadd_rn(acc, __fmul_rn(row[d], row[d]));
    g_sc[i] = acc;
}

__global__ void k_cbb(const float* __restrict__ cb) {
    size_t i = (size_t)blockIdx.x * blockDim.x + threadIdx.x;
    if (i >= (size_t)NQ * KK * DIMD) return;
    g_cbb[i] = __float2bfloat16(cb[i]);
}

// exact sum(x*x) (proven order) + bf16 conversion of residual into [vec][d]
__global__ void k_sx_xb(const float* __restrict__ res) {
    int n = blockIdx.x * blockDim.x + threadIdx.x;
    if (n >= NN) return;
    int b = n / TT, t = n - b * TT;
    const float* p = res + (size_t)b * (DIMD * TT) + t;
    __nv_bfloat16* xb = g_xb + (size_t)n * DIMD;
    float acc = 0.f;
    for (int d = 0; d < DIMD; ++d) {
        float v = p[(size_t)d * TT];
        acc = __fadd_rn(acc, __fmul_rn(v, v));
        xb[d] = __float2bfloat16(v);
    }
    g_sx[n] = acc;
}

// ---------------------------------------------------------------------------
// Approx score GEMM + fused tile-local candidate collection.
// score[vec][k] = sc[k] - 2 * dot_bf16(x_vec, c_k). Instead of storing all
// scores, each CTA emits per-vector: tile-min and <=TCAP entries within
// MARGIN of the tile-min (provable superset of final candidates).
__global__ __launch_bounds__(256, 2)
void k_gemm(int q) {
    extern __shared__ __align__(1024) char smArena[];

    int tid = threadIdx.x;
    int wid = tid >> 5, lane = tid & 31;
    int wm = (wid & 1) * 64;          // warp m offset (2 warps over M)
    int wn = (wid >> 1) * 32;         // warp n offset (4 warps over N)
    int n0m = blockIdx.x * GM;
    int k0n = blockIdx.y * GN;

    const __nv_bfloat16* cbb = g_cbb + (size_t)q * KK * DIMD;
    uint32_t sbase = smem_u32(smArena);
    uint32_t sa[2] = { sbase,               sbase + TILE_B };
    uint32_t sb[2] = { sbase + 2 * TILE_B,  sbase + 3 * TILE_B };

    int fr[4], fj[4];
#pragma unroll
    for (int it = 0; it < 4; ++it) {
        int idx = it * 256 + tid;
        fr[it] = idx >> 3;
        fj[it] = idx & 7;
    }

    auto fill = [&](int c, int buf) {
#pragma unroll
        for (int it = 0; it < 4; ++it) {
            int r = fr[it], j = fj[it];
            uint32_t soff = SWZ128(r * 128 + j * 16);
            cpasync16(sa[buf] + soff,
                      g_xb + (size_t)(n0m + r) * DIMD + c * GKC + j * 8);
            cpasync16(sb[buf] + soff,
                      cbb + (size_t)(k0n + r) * DIMD + c * GKC + j * 8);
        }
    };

    float acc[4][4][4];
#pragma unroll
    for (int i = 0; i < 4; ++i)
#pragma unroll
        for (int j = 0; j < 4; ++j)
#pragma unroll
            for (int f = 0; f < 4; ++f) acc[i][j][f] = 0.f;

    int aRow = lane & 15, aHalf = (lane >> 4) & 1;
    int bRow = (lane & 7) + ((lane >> 4) << 3);
    int bHalf = (lane >> 3) & 1;

    fill(0, 0);
    CP_COMMIT();

    for (int c = 0; c < NKCH; ++c) {
        int buf = c & 1;
        if (c < NKCH - 1) {
            fill(c + 1, buf ^ 1);
            CP_COMMIT();
            asm volatile("cp.async.wait_group 1;" ::: "memory");
        } else {
            asm volatile("cp.async.wait_group 0;" ::: "memory");
        }
        __syncthreads();

#pragma unroll
        for (int ks = 0; ks < 4; ++ks) {
            int kof = ks * 16;
            uint32_t af[4][4], bf[2][4];
#pragma unroll
            for (int i = 0; i < 4; ++i) {
                int row = wm + i * 16 + aRow;
                ldm_x4(af[i], sa[buf] + SWZ128(row * 128 + (kof + aHalf * 8) * 2));
            }
#pragma unroll
            for (int j = 0; j < 2; ++j) {
                int row = wn + j * 16 + bRow;
                ldm_x4(bf[j], sb[buf] + SWZ128(row * 128 + (kof + bHalf * 8) * 2));
            }
#pragma unroll
            for (int i = 0; i < 4; ++i) {
                mma_bf16(acc[i][0], af[i], &bf[0][0]);
                mma_bf16(acc[i][1], af[i], &bf[0][2]);
                mma_bf16(acc[i][2], af[i], &bf[1][0]);
                mma_bf16(acc[i][3], af[i], &bf[1][2]);
            }
        }
        __syncthreads();   // all warps done with buf; also guards arena reuse below
    }

    // ---- fused epilogue: tile-local min + candidate collection ----
    // arena reuse (post-sync): s_min / s_cnt / s_ck / s_cs
    unsigned* s_min = (unsigned*)smArena;                    // [128]
    int*      s_cnt = (int*)(smArena + 512);                 // [128]
    int*      s_ck  = (int*)(smArena + 1024);                // [128][TCAP]
    float*    s_cs  = (float*)(smArena + 1024 + 128 * TCAP * 4); // [128][TCAP]

    if (tid < GM) { s_min[tid] = 0xFFFFFFFFu; s_cnt[tid] = 0; }
    __syncthreads();

    const float* scp = g_sc + q * KK + k0n;

    // pass 1: per-row mins
#pragma unroll
    for (int i = 0; i < 4; ++i) {
        int r0 = wm + i * 16 + (lane >> 2);
        int r1 = r0 + 8;
        float m0 = 3.4e38f, m1 = 3.4e38f;
#pragma unroll
        for (int j = 0; j < 4; ++j) {
            int nc = wn + j * 8 + 2 * (lane & 3);
            float s0 = __fmaf_rn(-2.0f, acc[i][j][0], scp[nc]);
            float s1 = __fmaf_rn(-2.0f, acc[i][j][1], scp[nc + 1]);
            float s2 = __fmaf_rn(-2.0f, acc[i][j][2], scp[nc]);
            float s3 = __fmaf_rn(-2.0f, acc[i][j][3], scp[nc + 1]);
            m0 = fminf(m0, fminf(s0, s1));
            m1 = fminf(m1, fminf(s2, s3));
        }
        atomicMin(&s_min[r0], fflip(m0));
        atomicMin(&s_min[r1], fflip(m1));
    }
    __syncthreads();

    // pass 2: append entries within MARGIN of tile-min
#pragma unroll
    for (int i = 0; i < 4; ++i) {
        int r0 = wm + i * 16 + (lane >> 2);
        int r1 = r0 + 8;
        float thr0 = funflip(s_min[r0]) + MARGIN;
        float thr1 = funflip(s_min[r1]) + MARGIN;
#pragma unroll
        for (int j = 0; j < 4; ++j) {
            int nc = wn + j * 8 + 2 * (lane & 3);
            float s0 = __fmaf_rn(-2.0f, acc[i][j][0], scp[nc]);
            float s1 = __fmaf_rn(-2.0f, acc[i][j][1], scp[nc + 1]);
            float s2 = __fmaf_rn(-2.0f, acc[i][j][2], scp[nc]);
            float s3 = __fmaf_rn(-2.0f, acc[i][j][3], scp[nc + 1]);
            if (s0 <= thr0) {
                int p = atomicAdd(&s_cnt[r0], 1);
                if (p < TCAP) { s_ck[r0 * TCAP + p] = k0n + nc;     s_cs[r0 * TCAP + p] = s0; }
            }
            if (s1 <= thr0) {
                int p = atomicAdd(&s_cnt[r0], 1);
                if (p < TCAP) { s_ck[r0 * TCAP + p] = k0n + nc + 1; s_cs[r0 * TCAP + p] = s1; }
            }
            if (s2 <= thr1) {
                int p = atomicAdd(&s_cnt[r1], 1);
                if (p < TCAP) { s_ck[r1 * TCAP + p] = k0n + nc;     s_cs[r1 * TCAP + p] = s2; }
            }
            if (s3 <= thr1) {
                int p = atomicAdd(&s_cnt[r1], 1);
                if (p < TCAP) { s_ck[r1 * TCAP + p] = k0n + nc + 1; s_cs[r1 * TCAP + p] = s3; }
            }
        }
    }
    __syncthreads();

    // write per-(vector, n-tile) summary
    if (tid < GM) {
        int v = n0m + tid;
        int nt = blockIdx.y;
        size_t sidx = (size_t)v * NT + nt;
        g_tmin[sidx] = funflip(s_min[tid]);
        int c = s_cnt[tid];
        g_tcnt[sidx] = c;
        int cw = c < TCAP ? c : TCAP;
        for (int e = 0; e < cw; ++e) {
            g_tck[sidx * TCAP + e] = s_ck[tid * TCAP + e];
            g_tcs[sidx * TCAP + e] = s_cs[tid * TCAP + e];
        }
    }
}

// ---------------------------------------------------------------------------
// Merge: per vector, reduce 16 tile summaries -> final candidates.
__global__ __launch_bounds__(256)
void k_merge() {
    int v = blockIdx.x * blockDim.x + threadIdx.x;
    if (v >= NN) return;
    size_t base = (size_t)v * NT;

    float fmin = 3.4e38f;
#pragma unroll
    for (int nt = 0; nt < NT; ++nt)
        fmin = fminf(fmin, g_tmin[base + nt]);
    float thr = fmin + MARGIN;

    int cnt = 0;
    bool ovf = false;
#pragma unroll
    for (int nt = 0; nt < NT; ++nt) {
        float tm = g_tmin[base + nt];
        int c = g_tcnt[base + nt];
        if (c > TCAP) {
            if (tm <= thr) ovf = true;   // dropped entry might qualify
            c = TCAP;
        }
        for (int e = 0; e < c; ++e) {
            if (g_tcs[(base + nt) * TCAP + e] <= thr) {
                if (cnt < CAP) g_cand[v * CAP + cnt] = g_tck[(base + nt) * TCAP + e];
                ++cnt;
            }
        }
    }
    if (ovf) cnt = KK;    // force full exact scan fallback
    g_cnt[v] = cnt;
}

// ---------------------------------------------------------------------------
// Exact argmin, warp-per-vector (bitwise-proven fp32 chains; tie -> lowest k).
__global__ __launch_bounds__(256)
void k_exact(const float* __restrict__ res, const float* __restrict__ cbq,
             int q, float* __restrict__ out) {
    int v = blockIdx.x * 8 + (threadIdx.x >> 5);
    int lane = threadIdx.x & 31;
    if (v >= NN) return;
    int b = v / TT, t = v - b * TT;
    int cnt = g_cnt[v];
    int bi;
    if (cnt == 1) {
        bi = g_cand[v * CAP];
    } else {
        const float* xp = res + (size_t)b * (DIMD * TT) + t;
        float sx = g_sx[v];
        const float* scq = g_sc + q * KK;
        float bd = 3.4e38f;
        int   bk = KK;
        if (cnt <= CAP) {
            if (lane < cnt) {
                int k = g_cand[v * CAP + lane];
                const float* crow = cbq + (size_t)k * DIMD;
                float dot = 0.f;
                for (int d = 0; d < DIMD; ++d)
                    dot = __fmaf_rn(xp[(size_t)d * TT], crow[d], dot);
                bd = __fadd_rn(__fadd_rn(sx, -__fmul_rn(2.0f, dot)), scq[k]);
                bk = k;
            }
        } else {
            for (int k = lane; k < KK; k += 32) {
                const float* crow = cbq + (size_t)k * DIMD;
                float dot = 0.f;
                for (int d = 0; d < DIMD; ++d)
                    dot = __fmaf_rn(xp[(size_t)d * TT], crow[d], dot);
                float dist = __fadd_rn(__fadd_rn(sx, -__fmul_rn(2.0f, dot)),
                                       scq[k]);
                if (dist < bd) { bd = dist; bk = k; }
            }
        }
#pragma unroll
        for (int o = 16; o > 0; o >>= 1) {
            float od = __shfl_xor_sync(0xFFFFFFFFu, bd, o);
            int   ok = __shfl_xor_sync(0xFFFFFFFFu, bk, o);
            if (od < bd || (od == bd && ok < bk)) { bd = od; bk = ok; }
        }
        bi = bk;
    }
    if (lane == 0) {
        g_idx[v] = bi;
        out[IDX_OFF + (size_t)b * (NQ * TT) + (size_t)q * TT + t] = (float)bi;
    }
}

// ---------------------------------------------------------------------------
// Update kernel (bitwise-proven): straight-through quantize, output accum,
// residual update, per-block loss partial.
__global__ __launch_bounds__(256)
void k_update(const float* __restrict__ res_in, const float* __restrict__ cbq,
              int q, float* __restrict__ out) {
    int tid = threadIdx.x;
    int nl = tid & 63, dc = tid >> 6;
    int n = blockIdx.x * 64 + nl;
    int b = n / TT, t = n - b * TT;
    int k = g_idx[n];
    const float* crow = cbq + (size_t)k * DIMD;
    size_t base = (size_t)b * (DIMD * TT) + t;

    double lacc = 0.0;
    int d0 = dc * 128;
    for (int d = d0; d < d0 + 128; ++d) {
        size_t off = base + (size_t)d * TT;
        float r = res_in[off];
        float c = crow[d];
        float t1 = __fadd_rn(c, -r);
        float qo = __fadd_rn(r, t1);
        float qprev = (q == 0) ? 0.f : out[off];
        out[off]   = __fadd_rn(qprev, qo);
        g_res[off] = __fadd_rn(r, -qo);
        lacc += (double)t1 * (double)t1;
    }

    __shared__ double sred[256];
    sred[tid] = lacc;
    __syncthreads();
    for (int s = 128; s > 0; s >>= 1) {
        if (tid < s) sred[tid] += sred[tid + s];
        __syncthreads();
    }
    if (tid == 0) g_partial[q * UPD_BLOCKS + blockIdx.x] = sred[0];
}

__global__ void k_final(float* __restrict__ out) {
    __shared__ float lq[NQ];
    int q = threadIdx.x;
    if (q < NQ) {
        double s = 0.0;
        for (int i = 0; i < UPD_BLOCKS; ++i) s += g_partial[q * UPD_BLOCKS + i];
        lq[q] = (float)(s / (double)QOUT_ELEMS);
    }
    __syncthreads();
    if (q == 0) {
        float tl = 0.f;
        for (int i = 0; i < NQ; ++i) tl = __fadd_rn(tl, lq[i]);
        out[LOSS_OFF] = tl;
    }
}

// ---------------------------------------------------------------------------
extern "C" void kernel_launch(void* const* d_in, const int* in_sizes, int n_in,
                              void* d_out, int out_size) {
    const float* x  = (const float*)d_in[0];
    const float* cb = (const float*)d_in[1];
    float* out = (float*)d_out;

    void* resg_v = nullptr;
    cudaGetSymbolAddress(&resg_v, g_res);
    const float* resg = (const float*)resg_v;

    cudaFuncSetAttribute(k_gemm, cudaFuncAttributeMaxDynamicSharedMemorySize,
                         GEMM_SMEM);

    k_sc<<<(NQ * KK + 255) / 256, 256>>>(cb);
    k_cbb<<<(int)(((size_t)NQ * KK * DIMD + 255) / 256), 256>>>(cb);

    const float* res = x;   // stage 0 reads x directly
    for (int q = 0; q < NQ; ++q) {
        const float* cbq = cb + (size_t)q * KK * DIMD;
        k_sx_xb<<<(NN + 255) / 256, 256>>>(res);
        dim3 gg(MT, NT);
        k_gemm<<<gg, 256, GEMM_SMEM>>>(q);
        k_merge<<<(NN + 255) / 256, 256>>>();
        k_exact<<<NN / 8, 256>>>(res, cbq, q, out);
        k_update<<<UPD_BLOCKS, 256>>>(res, cbq, q, out);
        res = resg;
    }
    k_final<<<1, 32>>>(out);
}

// round 13
// speedup vs baseline: 5.8936x; 1.0045x over previous
#include <cuda_runtime.h>
#include <cuda_bf16.h>
#include <cstdint>
#include <cstddef>

// Problem constants
#define BB   32
#define TT   1500
#define DIMD 512
#define NQ   8
#define KK   2048
#define NN   (BB*TT)              // 48000 vectors
#define QOUT_ELEMS (BB*DIMD*TT)   // 24576000
#define IDX_OFF QOUT_ELEMS
#define LOSS_OFF (QOUT_ELEMS + BB*NQ*TT)

#define CAP     16                // max candidates per vector for exact pass
#define TCAP    4                 // max candidates per (vector, n-tile)
#define MARGIN  1e-3f             // ~28 sigma of bf16-rounding dist error
#define UPD_BLOCKS (NN/64)        // 750

// GEMM tiling (mma.sync m16n8k16 bf16 — baseline PTX, valid on sm_100)
#define GM 128
#define GN 128
#define GKC 64
#define NKCH (DIMD/GKC)           // 8
#define MT (NN/GM)                // 375
#define NT (KK/GN)                // 16
#define TILE_B (GM*128)           // 16384 bytes per tile buffer
#define GEMM_SMEM (4*TILE_B)      // 64 KB dynamic

// Scratch (static device globals; no runtime allocation)
__device__ float          g_res[(size_t)NN * DIMD];      // residual [b,d,t]
__device__ float          g_sx[NN];                      // exact row sums
__device__ float          g_sc[NQ * KK];                 // exact codeword sums
__device__ __nv_bfloat16  g_xb[(size_t)NN * DIMD];       // bf16 residual [vec][d]
__device__ __nv_bfloat16  g_cbb[(size_t)NQ * KK * DIMD]; // bf16 codebooks [k][d]
// per-(vector, n-tile) summaries (replace the 393MB g_D score matrix)
__device__ float          g_tmin[NN * NT];
__device__ int            g_tcnt[NN * NT];
__device__ int            g_tck[NN * NT * TCAP];
__device__ float          g_tcs[NN * NT * TCAP];
__device__ int            g_cand[NN * CAP];
__device__ int            g_cnt[NN];
__device__ int            g_idx[NN];
__device__ double         g_partial[NQ * UPD_BLOCKS];

#define SWZ128(o) ((o) ^ (((o) >> 3) & 0x70))

__device__ __forceinline__ uint32_t smem_u32(const void* p) {
    uint32_t a;
    asm("{ .reg .u64 t; cvta.to.shared.u64 t, %1; cvt.u32.u64 %0, t; }"
        : "=r"(a) : "l"(p));
    return a;
}

// order-preserving float <-> uint for atomicMin
__device__ __forceinline__ unsigned fflip(float f) {
    unsigned u = __float_as_uint(f);
    return u ^ (unsigned)(((int)u >> 31) | 0x80000000);
}
__device__ __forceinline__ float funflip(unsigned u) {
    unsigned m = (u >> 31) ? 0x80000000u : 0xFFFFFFFFu;
    return __uint_as_float(u ^ m);
}

__device__ __forceinline__ void ldm_x4(uint32_t* r, uint32_t addr) {
    asm volatile("ldmatrix.sync.aligned.m8n8.x4.shared.b16 {%0,%1,%2,%3}, [%4];"
                 : "=r"(r[0]), "=r"(r[1]), "=r"(r[2]), "=r"(r[3]) : "r"(addr));
}

__device__ __forceinline__ void mma_bf16(float* c, const uint32_t* a,
                                         const uint32_t* b) {
    asm volatile(
        "mma.sync.aligned.m16n8k16.row.col.f32.bf16.bf16.f32 "
        "{%0,%1,%2,%3}, {%4,%5,%6,%7}, {%8,%9}, {%0,%1,%2,%3};"
        : "+f"(c[0]), "+f"(c[1]), "+f"(c[2]), "+f"(c[3])
        : "r"(a[0]), "r"(a[1]), "r"(a[2]), "r"(a[3]), "r"(b[0]), "r"(b[1]));
}

__device__ __forceinline__ void cpasync16(uint32_t dst, const void* src) {
    asm volatile("cp.async.cg.shared.global [%0], [%1], 16;"
                 :: "r"(dst), "l"(src) : "memory");
}
#define CP_COMMIT() asm volatile("cp.async.commit_group;" ::: "memory")

// ---------------------------------------------------------------------------
// Exact precompute kernels (bitwise-proven arithmetic orders)
__global__ void k_sc(const float* __restrict__ cb) {
    int i = blockIdx.x * blockDim.x + threadIdx.x;
    if (i >= NQ * KK) return;
    const float* row = cb + (size_t)i * DIMD;
    float acc = 0.f;
    for (int d = 0; d < DIMD; ++d)
        acc = __fadd_rn(acc, __fmul_rn(row[d], row[d]));
    g_sc[i] = acc;
}

__global__ void k_cbb(const float* __restrict__ cb) {
    size_t i = (size_t)blockIdx.x * blockDim.x + threadIdx.x;
    if (i >= (size_t)NQ * KK * DIMD) return;
    g_cbb[i] = __float2bfloat16(cb[i]);
}

// exact sum(x*x) (proven order) + bf16 conversion of residual into [vec][d]
__global__ void k_sx_xb(const float* __restrict__ res) {
    int n = blockIdx.x * blockDim.x + threadIdx.x;
    if (n >= NN) return;
    int b = n / TT, t = n - b * TT;
    const float* p = res + (size_t)b * (DIMD * TT) + t;
    __nv_bfloat16* xb = g_xb + (size_t)n * DIMD;
    float acc = 0.f;
    for (int d = 0; d < DIMD; ++d) {
        float v = p[(size_t)d * TT];
        acc = __fadd_rn(acc, __fmul_rn(v, v));
        xb[d] = __float2bfloat16(v);
    }
    g_sx[n] = acc;
}

// ---------------------------------------------------------------------------
// Approx score GEMM + fused tile-local candidate collection.
// score[vec][k] = sc[k] - 2 * dot_bf16(x_vec, c_k). Instead of storing all
// scores, each CTA emits per-vector: tile-min and <=TCAP entries within
// MARGIN of the tile-min (provable superset of final candidates).
__global__ __launch_bounds__(256, 2)
void k_gemm(int q) {
    extern __shared__ __align__(1024) char smArena[];

    int tid = threadIdx.x;
    int wid = tid >> 5, lane = tid & 31;
    int wm = (wid & 1) * 64;          // warp m offset (2 warps over M)
    int wn = (wid >> 1) * 32;         // warp n offset (4 warps over N)
    int n0m = blockIdx.x * GM;
    int k0n = blockIdx.y * GN;

    const __nv_bfloat16* cbb = g_cbb + (size_t)q * KK * DIMD;
    uint32_t sbase = smem_u32(smArena);
    uint32_t sa[2] = { sbase,               sbase + TILE_B };
    uint32_t sb[2] = { sbase + 2 * TILE_B,  sbase + 3 * TILE_B };

    int fr[4], fj[4];
#pragma unroll
    for (int it = 0; it < 4; ++it) {
        int idx = it * 256 + tid;
        fr[it] = idx >> 3;
        fj[it] = idx & 7;
    }

    auto fill = [&](int c, int buf) {
#pragma unroll
        for (int it = 0; it < 4; ++it) {
            int r = fr[it], j = fj[it];
            uint32_t soff = SWZ128(r * 128 + j * 16);
            cpasync16(sa[buf] + soff,
                      g_xb + (size_t)(n0m + r) * DIMD + c * GKC + j * 8);
            cpasync16(sb[buf] + soff,
                      cbb + (size_t)(k0n + r) * DIMD + c * GKC + j * 8);
        }
    };

    float acc[4][4][4];
#pragma unroll
    for (int i = 0; i < 4; ++i)
#pragma unroll
        for (int j = 0; j < 4; ++j)
#pragma unroll
            for (int f = 0; f < 4; ++f) acc[i][j][f] = 0.f;

    int aRow = lane & 15, aHalf = (lane >> 4) & 1;
    int bRow = (lane & 7) + ((lane >> 4) << 3);
    int bHalf = (lane >> 3) & 1;

    fill(0, 0);
    CP_COMMIT();

    for (int c = 0; c < NKCH; ++c) {
        int buf = c & 1;
        if (c < NKCH - 1) {
            fill(c + 1, buf ^ 1);
            CP_COMMIT();
            asm volatile("cp.async.wait_group 1;" ::: "memory");
        } else {
            asm volatile("cp.async.wait_group 0;" ::: "memory");
        }
        __syncthreads();

#pragma unroll
        for (int ks = 0; ks < 4; ++ks) {
            int kof = ks * 16;
            uint32_t af[4][4], bf[2][4];
#pragma unroll
            for (int i = 0; i < 4; ++i) {
                int row = wm + i * 16 + aRow;
                ldm_x4(af[i], sa[buf] + SWZ128(row * 128 + (kof + aHalf * 8) * 2));
            }
#pragma unroll
            for (int j = 0; j < 2; ++j) {
                int row = wn + j * 16 + bRow;
                ldm_x4(bf[j], sb[buf] + SWZ128(row * 128 + (kof + bHalf * 8) * 2));
            }
#pragma unroll
            for (int i = 0; i < 4; ++i) {
                mma_bf16(acc[i][0], af[i], &bf[0][0]);
                mma_bf16(acc[i][1], af[i], &bf[0][2]);
                mma_bf16(acc[i][2], af[i], &bf[1][0]);
                mma_bf16(acc[i][3], af[i], &bf[1][2]);
            }
        }
        __syncthreads();   // all warps done with buf; also guards arena reuse below
    }

    // ---- fused epilogue: tile-local min + candidate collection ----
    // arena reuse (post-sync): s_min / s_cnt / s_ck / s_cs
    unsigned* s_min = (unsigned*)smArena;                    // [128]
    int*      s_cnt = (int*)(smArena + 512);                 // [128]
    int*      s_ck  = (int*)(smArena + 1024);                // [128][TCAP]
    float*    s_cs  = (float*)(smArena + 1024 + 128 * TCAP * 4); // [128][TCAP]

    if (tid < GM) { s_min[tid] = 0xFFFFFFFFu; s_cnt[tid] = 0; }
    __syncthreads();

    const float* scp = g_sc + q * KK + k0n;

    // pass 1: per-row mins
#pragma unroll
    for (int i = 0; i < 4; ++i) {
        int r0 = wm + i * 16 + (lane >> 2);
        int r1 = r0 + 8;
        float m0 = 3.4e38f, m1 = 3.4e38f;
#pragma unroll
        for (int j = 0; j < 4; ++j) {
            int nc = wn + j * 8 + 2 * (lane & 3);
            float s0 = __fmaf_rn(-2.0f, acc[i][j][0], scp[nc]);
            float s1 = __fmaf_rn(-2.0f, acc[i][j][1], scp[nc + 1]);
            float s2 = __fmaf_rn(-2.0f, acc[i][j][2], scp[nc]);
            float s3 = __fmaf_rn(-2.0f, acc[i][j][3], scp[nc + 1]);
            m0 = fminf(m0, fminf(s0, s1));
            m1 = fminf(m1, fminf(s2, s3));
        }
        atomicMin(&s_min[r0], fflip(m0));
        atomicMin(&s_min[r1], fflip(m1));
    }
    __syncthreads();

    // pass 2: append entries within MARGIN of tile-min
#pragma unroll
    for (int i = 0; i < 4; ++i) {
        int r0 = wm + i * 16 + (lane >> 2);
        int r1 = r0 + 8;
        float thr0 = funflip(s_min[r0]) + MARGIN;
        float thr1 = funflip(s_min[r1]) + MARGIN;
#pragma unroll
        for (int j = 0; j < 4; ++j) {
            int nc = wn + j * 8 + 2 * (lane & 3);
            float s0 = __fmaf_rn(-2.0f, acc[i][j][0], scp[nc]);
            float s1 = __fmaf_rn(-2.0f, acc[i][j][1], scp[nc + 1]);
            float s2 = __fmaf_rn(-2.0f, acc[i][j][2], scp[nc]);
            float s3 = __fmaf_rn(-2.0f, acc[i][j][3], scp[nc + 1]);
            if (s0 <= thr0) {
                int p = atomicAdd(&s_cnt[r0], 1);
                if (p < TCAP) { s_ck[r0 * TCAP + p] = k0n + nc;     s_cs[r0 * TCAP + p] = s0; }
            }
            if (s1 <= thr0) {
                int p = atomicAdd(&s_cnt[r0], 1);
                if (p < TCAP) { s_ck[r0 * TCAP + p] = k0n + nc + 1; s_cs[r0 * TCAP + p] = s1; }
            }
            if (s2 <= thr1) {
                int p = atomicAdd(&s_cnt[r1], 1);
                if (p < TCAP) { s_ck[r1 * TCAP + p] = k0n + nc;     s_cs[r1 * TCAP + p] = s2; }
            }
            if (s3 <= thr1) {
                int p = atomicAdd(&s_cnt[r1], 1);
                if (p < TCAP) { s_ck[r1 * TCAP + p] = k0n + nc + 1; s_cs[r1 * TCAP + p] = s3; }
            }
        }
    }
    __syncthreads();

    // write per-(vector, n-tile) summary
    if (tid < GM) {
        int v = n0m + tid;
        int nt = blockIdx.y;
        size_t sidx = (size_t)v * NT + nt;
        g_tmin[sidx] = funflip(s_min[tid]);
        int c = s_cnt[tid];
        g_tcnt[sidx] = c;
        int cw = c < TCAP ? c : TCAP;
        for (int e = 0; e < cw; ++e) {
            g_tck[sidx * TCAP + e] = s_ck[tid * TCAP + e];
            g_tcs[sidx * TCAP + e] = s_cs[tid * TCAP + e];
        }
    }
}

// ---------------------------------------------------------------------------
// Merge: per vector, reduce 16 tile summaries -> final candidates.
__global__ __launch_bounds__(256)
void k_merge() {
    int v = blockIdx.x * blockDim.x + threadIdx.x;
    if (v >= NN) return;
    size_t base = (size_t)v * NT;

    float fmin = 3.4e38f;
#pragma unroll
    for (int nt = 0; nt < NT; ++nt)
        fmin = fminf(fmin, g_tmin[base + nt]);
    float thr = fmin + MARGIN;

    int cnt = 0;
    bool ovf = false;
#pragma unroll
    for (int nt = 0; nt < NT; ++nt) {
        float tm = g_tmin[base + nt];
        int c = g_tcnt[base + nt];
        if (c > TCAP) {
            if (tm <= thr) ovf = true;   // dropped entry might qualify
            c = TCAP;
        }
        for (int e = 0; e < c; ++e) {
            if (g_tcs[(base + nt) * TCAP + e] <= thr) {
                if (cnt < CAP) g_cand[v * CAP + cnt] = g_tck[(base + nt) * TCAP + e];
                ++cnt;
            }
        }
    }
    if (ovf) cnt = KK;    // force full exact scan fallback
    g_cnt[v] = cnt;
}

// ---------------------------------------------------------------------------
// Exact argmin, warp-per-vector (bitwise-proven fp32 chains; tie -> lowest k).
__global__ __launch_bounds__(256)
void k_exact(const float* __restrict__ res, const float* __restrict__ cbq,
             int q, float* __restrict__ out) {
    int v = blockIdx.x * 8 + (threadIdx.x >> 5);
    int lane = threadIdx.x & 31;
    if (v >= NN) return;
    int b = v / TT, t = v - b * TT;
    int cnt = g_cnt[v];
    int bi;
    if (cnt == 1) {
        bi = g_cand[v * CAP];
    } else {
        const float* xp = res + (size_t)b * (DIMD * TT) + t;
        float sx = g_sx[v];
        const float* scq = g_sc + q * KK;
        float bd = 3.4e38f;
        int   bk = KK;
        if (cnt <= CAP) {
            if (lane < cnt) {
                int k = g_cand[v * CAP + lane];
                const float* crow = cbq + (size_t)k * DIMD;
                float dot = 0.f;
                for (int d = 0; d < DIMD; ++d)
                    dot = __fmaf_rn(xp[(size_t)d * TT], crow[d], dot);
                bd = __fadd_rn(__fadd_rn(sx, -__fmul_rn(2.0f, dot)), scq[k]);
                bk = k;
            }
        } else {
            for (int k = lane; k < KK; k += 32) {
                const float* crow = cbq + (size_t)k * DIMD;
                float dot = 0.f;
                for (int d = 0; d < DIMD; ++d)
                    dot = __fmaf_rn(xp[(size_t)d * TT], crow[d], dot);
                float dist = __fadd_rn(__fadd_rn(sx, -__fmul_rn(2.0f, dot)),
                                       scq[k]);
                if (dist < bd) { bd = dist; bk = k; }
            }
        }
#pragma unroll
        for (int o = 16; o > 0; o >>= 1) {
            float od = __shfl_xor_sync(0xFFFFFFFFu, bd, o);
            int   ok = __shfl_xor_sync(0xFFFFFFFFu, bk, o);
            if (od < bd || (od == bd && ok < bk)) { bd = od; bk = ok; }
        }
        bi = bk;
    }
    if (lane == 0) {
        g_idx[v] = bi;
        out[IDX_OFF + (size_t)b * (NQ * TT) + (size_t)q * TT + t] = (float)bi;
    }
}

// ---------------------------------------------------------------------------
// Update kernel (bitwise-proven): straight-through quantize, output accum,
// residual update, per-block loss partial.
__global__ __launch_bounds__(256)
void k_update(const float* __restrict__ res_in, const float* __restrict__ cbq,
              int q, float* __restrict__ out) {
    int tid = threadIdx.x;
    int nl = tid & 63, dc = tid >> 6;
    int n = blockIdx.x * 64 + nl;
    int b = n / TT, t = n - b * TT;
    int k = g_idx[n];
    const float* crow = cbq + (size_t)k * DIMD;
    size_t base = (size_t)b * (DIMD * TT) + t;

    double lacc = 0.0;
    int d0 = dc * 128;
    for (int d = d0; d < d0 + 128; ++d) {
        size_t off = base + (size_t)d * TT;
        float r = res_in[off];
        float c = crow[d];
        float t1 = __fadd_rn(c, -r);
        float qo = __fadd_rn(r, t1);
        float qprev = (q == 0) ? 0.f : out[off];
        out[off]   = __fadd_rn(qprev, qo);
        g_res[off] = __fadd_rn(r, -qo);
        lacc += (double)t1 * (double)t1;
    }

    __shared__ double sred[256];
    sred[tid] = lacc;
    __syncthreads();
    for (int s = 128; s > 0; s >>= 1) {
        if (tid < s) sred[tid] += sred[tid + s];
        __syncthreads();
    }
    if (tid == 0) g_partial[q * UPD_BLOCKS + blockIdx.x] = sred[0];
}

__global__ void k_final(float* __restrict__ out) {
    __shared__ float lq[NQ];
    int q = threadIdx.x;
    if (q < NQ) {
        double s = 0.0;
        for (int i = 0; i < UPD_BLOCKS; ++i) s += g_partial[q * UPD_BLOCKS + i];
        lq[q] = (float)(s / (double)QOUT_ELEMS);
    }
    __syncthreads();
    if (q == 0) {
        float tl = 0.f;
        for (int i = 0; i < NQ; ++i) tl = __fadd_rn(tl, lq[i]);
        out[LOSS_OFF] = tl;
    }
}

// ---------------------------------------------------------------------------
extern "C" void kernel_launch(void* const* d_in, const int* in_sizes, int n_in,
                              void* d_out, int out_size) {
    const float* x  = (const float*)d_in[0];
    const float* cb = (const float*)d_in[1];
    float* out = (float*)d_out;

    void* resg_v = nullptr;
    cudaGetSymbolAddress(&resg_v, g_res);
    const float* resg = (const float*)resg_v;

    cudaFuncSetAttribute(k_gemm, cudaFuncAttributeMaxDynamicSharedMemorySize,
                         GEMM_SMEM);

    k_sc<<<(NQ * KK + 255) / 256, 256>>>(cb);
    k_cbb<<<(int)(((size_t)NQ * KK * DIMD + 255) / 256), 256>>>(cb);

    const float* res = x;   // stage 0 reads x directly
    for (int q = 0; q < NQ; ++q) {
        const float* cbq = cb + (size_t)q * KK * DIMD;
        k_sx_xb<<<(NN + 255) / 256, 256>>>(res);
        dim3 gg(MT, NT);
        k_gemm<<<gg, 256, GEMM_SMEM>>>(q);
        k_merge<<<(NN + 255) / 256, 256>>>();
        k_exact<<<NN / 8, 256>>>(res, cbq, q, out);
        k_update<<<UPD_BLOCKS, 256>>>(res, cbq, q, out);
        res = resg;
    }
    k_final<<<1, 32>>>(out);
}

// round 14
// speedup vs baseline: 5.9046x; 1.0019x over previous
#include <cuda_runtime.h>
#include <cuda_bf16.h>
#include <cstdint>
#include <cstddef>

// Problem constants
#define BB   32
#define TT   1500
#define DIMD 512
#define NQ   8
#define KK   2048
#define NN   (BB*TT)              // 48000 vectors
#define QOUT_ELEMS (BB*DIMD*TT)   // 24576000
#define IDX_OFF QOUT_ELEMS
#define LOSS_OFF (QOUT_ELEMS + BB*NQ*TT)

#define CAP     16                // max candidates per vector for exact pass
#define TCAP    4                 // max candidates per (vector, n-tile)
#define MARGIN  1e-3f             // ~28 sigma of bf16-rounding dist error
#define UPD_BLOCKS (NN/64)        // 750

// GEMM tiling (mma.sync m16n8k16 bf16 — baseline PTX, valid on sm_100)
#define GM 128
#define GN 128
#define GKC 64
#define NKCH (DIMD/GKC)           // 8
#define MT (NN/GM)                // 375
#define NT (KK/GN)                // 16
#define TILE_B (GM*128)           // 16384 bytes per tile buffer
#define GEMM_SMEM (4*TILE_B)      // 64 KB dynamic

// Scratch (static device globals; no runtime allocation)
__device__ float          g_res[(size_t)NN * DIMD];      // residual [b,d,t]
__device__ float          g_sx[NN];                      // exact row sums
__device__ float          g_sc[NQ * KK];                 // exact codeword sums
__device__ __nv_bfloat16  g_xb[(size_t)NN * DIMD];       // bf16 residual [vec][d]
__device__ __nv_bfloat16  g_cbb[(size_t)NQ * KK * DIMD]; // bf16 codebooks [k][d]
// per-(vector, n-tile) summaries (replace the 393MB g_D score matrix)
__device__ float          g_tmin[NN * NT];
__device__ int            g_tcnt[NN * NT];
__device__ int            g_tck[NN * NT * TCAP];
__device__ float          g_tcs[NN * NT * TCAP];
__device__ int            g_cand[NN * CAP];
__device__ int            g_cnt[NN];
__device__ int            g_idx[NN];
__device__ double         g_partial[NQ * UPD_BLOCKS];

#define SWZ128(o) ((o) ^ (((o) >> 3) & 0x70))

__device__ __forceinline__ uint32_t smem_u32(const void* p) {
    uint32_t a;
    asm("{ .reg .u64 t; cvta.to.shared.u64 t, %1; cvt.u32.u64 %0, t; }"
        : "=r"(a) : "l"(p));
    return a;
}

// order-preserving float <-> uint for atomicMin
__device__ __forceinline__ unsigned fflip(float f) {
    unsigned u = __float_as_uint(f);
    return u ^ (unsigned)(((int)u >> 31) | 0x80000000);
}
__device__ __forceinline__ float funflip(unsigned u) {
    unsigned m = (u >> 31) ? 0x80000000u : 0xFFFFFFFFu;
    return __uint_as_float(u ^ m);
}

__device__ __forceinline__ void ldm_x4(uint32_t* r, uint32_t addr) {
    asm volatile("ldmatrix.sync.aligned.m8n8.x4.shared.b16 {%0,%1,%2,%3}, [%4];"
                 : "=r"(r[0]), "=r"(r[1]), "=r"(r[2]), "=r"(r[3]) : "r"(addr));
}

__device__ __forceinline__ void mma_bf16(float* c, const uint32_t* a,
                                         const uint32_t* b) {
    asm volatile(
        "mma.sync.aligned.m16n8k16.row.col.f32.bf16.bf16.f32 "
        "{%0,%1,%2,%3}, {%4,%5,%6,%7}, {%8,%9}, {%0,%1,%2,%3};"
        : "+f"(c[0]), "+f"(c[1]), "+f"(c[2]), "+f"(c[3])
        : "r"(a[0]), "r"(a[1]), "r"(a[2]), "r"(a[3]), "r"(b[0]), "r"(b[1]));
}

__device__ __forceinline__ void cpasync16(uint32_t dst, const void* src) {
    asm volatile("cp.async.cg.shared.global [%0], [%1], 16;"
                 :: "r"(dst), "l"(src) : "memory");
}
#define CP_COMMIT() asm volatile("cp.async.commit_group;" ::: "memory")

// ---------------------------------------------------------------------------
// Exact precompute kernels (bitwise-proven arithmetic orders)
__global__ void k_sc(const float* __restrict__ cb) {
    int i = blockIdx.x * blockDim.x + threadIdx.x;
    if (i >= NQ * KK) return;
    const float* row = cb + (size_t)i * DIMD;
    float acc = 0.f;
    for (int d = 0; d < DIMD; ++d)
        acc = __fadd_rn(acc, __fmul_rn(row[d], row[d]));
    g_sc[i] = acc;
}

__global__ void k_cbb(const float* __restrict__ cb) {
    size_t i = (size_t)blockIdx.x * blockDim.x + threadIdx.x;
    if (i >= (size_t)NQ * KK * DIMD) return;
    g_cbb[i] = __float2bfloat16(cb[i]);
}

// exact sum(x*x) (proven order) + bf16 conversion of residual into [vec][d]
__global__ void k_sx_xb(const float* __restrict__ res) {
    int n = blockIdx.x * blockDim.x + threadIdx.x;
    if (n >= NN) return;
    int b = n / TT, t = n - b * TT;
    const float* p = res + (size_t)b * (DIMD * TT) + t;
    __nv_bfloat16* xb = g_xb + (size_t)n * DIMD;
    float acc = 0.f;
    for (int d = 0; d < DIMD; ++d) {
        float v = p[(size_t)d * TT];
        acc = __fadd_rn(acc, __fmul_rn(v, v));
        xb[d] = __float2bfloat16(v);
    }
    g_sx[n] = acc;
}

// ---------------------------------------------------------------------------
// Approx score GEMM + fused tile-local candidate collection.
// score[vec][k] = sc[k] - 2 * dot_bf16(x_vec, c_k). Instead of storing all
// scores, each CTA emits per-vector: tile-min and <=TCAP entries within
// MARGIN of the tile-min (provable superset of final candidates).
__global__ __launch_bounds__(256, 2)
void k_gemm(int q) {
    extern __shared__ __align__(1024) char smArena[];

    int tid = threadIdx.x;
    int wid = tid >> 5, lane = tid & 31;
    int wm = (wid & 1) * 64;          // warp m offset (2 warps over M)
    int wn = (wid >> 1) * 32;         // warp n offset (4 warps over N)
    int n0m = blockIdx.x * GM;
    int k0n = blockIdx.y * GN;

    const __nv_bfloat16* cbb = g_cbb + (size_t)q * KK * DIMD;
    uint32_t sbase = smem_u32(smArena);
    uint32_t sa[2] = { sbase,               sbase + TILE_B };
    uint32_t sb[2] = { sbase + 2 * TILE_B,  sbase + 3 * TILE_B };

    int fr[4], fj[4];
#pragma unroll
    for (int it = 0; it < 4; ++it) {
        int idx = it * 256 + tid;
        fr[it] = idx >> 3;
        fj[it] = idx & 7;
    }

    auto fill = [&](int c, int buf) {
#pragma unroll
        for (int it = 0; it < 4; ++it) {
            int r = fr[it], j = fj[it];
            uint32_t soff = SWZ128(r * 128 + j * 16);
            cpasync16(sa[buf] + soff,
                      g_xb + (size_t)(n0m + r) * DIMD + c * GKC + j * 8);
            cpasync16(sb[buf] + soff,
                      cbb + (size_t)(k0n + r) * DIMD + c * GKC + j * 8);
        }
    };

    float acc[4][4][4];
#pragma unroll
    for (int i = 0; i < 4; ++i)
#pragma unroll
        for (int j = 0; j < 4; ++j)
#pragma unroll
            for (int f = 0; f < 4; ++f) acc[i][j][f] = 0.f;

    int aRow = lane & 15, aHalf = (lane >> 4) & 1;
    int bRow = (lane & 7) + ((lane >> 4) << 3);
    int bHalf = (lane >> 3) & 1;

    fill(0, 0);
    CP_COMMIT();

    for (int c = 0; c < NKCH; ++c) {
        int buf = c & 1;
        if (c < NKCH - 1) {
            fill(c + 1, buf ^ 1);
            CP_COMMIT();
            asm volatile("cp.async.wait_group 1;" ::: "memory");
        } else {
            asm volatile("cp.async.wait_group 0;" ::: "memory");
        }
        __syncthreads();

#pragma unroll
        for (int ks = 0; ks < 4; ++ks) {
            int kof = ks * 16;
            uint32_t af[4][4], bf[2][4];
#pragma unroll
            for (int i = 0; i < 4; ++i) {
                int row = wm + i * 16 + aRow;
                ldm_x4(af[i], sa[buf] + SWZ128(row * 128 + (kof + aHalf * 8) * 2));
            }
#pragma unroll
            for (int j = 0; j < 2; ++j) {
                int row = wn + j * 16 + bRow;
                ldm_x4(bf[j], sb[buf] + SWZ128(row * 128 + (kof + bHalf * 8) * 2));
            }
#pragma unroll
            for (int i = 0; i < 4; ++i) {
                mma_bf16(acc[i][0], af[i], &bf[0][0]);
                mma_bf16(acc[i][1], af[i], &bf[0][2]);
                mma_bf16(acc[i][2], af[i], &bf[1][0]);
                mma_bf16(acc[i][3], af[i], &bf[1][2]);
            }
        }
        __syncthreads();   // all warps done with buf; also guards arena reuse below
    }

    // ---- fused epilogue: tile-local min + candidate collection ----
    // arena reuse (post-sync): s_min / s_cnt / s_ck / s_cs
    unsigned* s_min = (unsigned*)smArena;                    // [128]
    int*      s_cnt = (int*)(smArena + 512);                 // [128]
    int*      s_ck  = (int*)(smArena + 1024);                // [128][TCAP]
    float*    s_cs  = (float*)(smArena + 1024 + 128 * TCAP * 4); // [128][TCAP]

    if (tid < GM) { s_min[tid] = 0xFFFFFFFFu; s_cnt[tid] = 0; }
    __syncthreads();

    const float* scp = g_sc + q * KK + k0n;

    // pass 1: per-row mins
#pragma unroll
    for (int i = 0; i < 4; ++i) {
        int r0 = wm + i * 16 + (lane >> 2);
        int r1 = r0 + 8;
        float m0 = 3.4e38f, m1 = 3.4e38f;
#pragma unroll
        for (int j = 0; j < 4; ++j) {
            int nc = wn + j * 8 + 2 * (lane & 3);
            float s0 = __fmaf_rn(-2.0f, acc[i][j][0], scp[nc]);
            float s1 = __fmaf_rn(-2.0f, acc[i][j][1], scp[nc + 1]);
            float s2 = __fmaf_rn(-2.0f, acc[i][j][2], scp[nc]);
            float s3 = __fmaf_rn(-2.0f, acc[i][j][3], scp[nc + 1]);
            m0 = fminf(m0, fminf(s0, s1));
            m1 = fminf(m1, fminf(s2, s3));
        }
        atomicMin(&s_min[r0], fflip(m0));
        atomicMin(&s_min[r1], fflip(m1));
    }
    __syncthreads();

    // pass 2: append entries within MARGIN of tile-min
#pragma unroll
    for (int i = 0; i < 4; ++i) {
        int r0 = wm + i * 16 + (lane >> 2);
        int r1 = r0 + 8;
        float thr0 = funflip(s_min[r0]) + MARGIN;
        float thr1 = funflip(s_min[r1]) + MARGIN;
#pragma unroll
        for (int j = 0; j < 4; ++j) {
            int nc = wn + j * 8 + 2 * (lane & 3);
            float s0 = __fmaf_rn(-2.0f, acc[i][j][0], scp[nc]);
            float s1 = __fmaf_rn(-2.0f, acc[i][j][1], scp[nc + 1]);
            float s2 = __fmaf_rn(-2.0f, acc[i][j][2], scp[nc]);
            float s3 = __fmaf_rn(-2.0f, acc[i][j][3], scp[nc + 1]);
            if (s0 <= thr0) {
                int p = atomicAdd(&s_cnt[r0], 1);
                if (p < TCAP) { s_ck[r0 * TCAP + p] = k0n + nc;     s_cs[r0 * TCAP + p] = s0; }
            }
            if (s1 <= thr0) {
                int p = atomicAdd(&s_cnt[r0], 1);
                if (p < TCAP) { s_ck[r0 * TCAP + p] = k0n + nc + 1; s_cs[r0 * TCAP + p] = s1; }
            }
            if (s2 <= thr1) {
                int p = atomicAdd(&s_cnt[r1], 1);
                if (p < TCAP) { s_ck[r1 * TCAP + p] = k0n + nc;     s_cs[r1 * TCAP + p] = s2; }
            }
            if (s3 <= thr1) {
                int p = atomicAdd(&s_cnt[r1], 1);
                if (p < TCAP) { s_ck[r1 * TCAP + p] = k0n + nc + 1; s_cs[r1 * TCAP + p] = s3; }
            }
        }
    }
    __syncthreads();

    // write per-(vector, n-tile) summary
    if (tid < GM) {
        int v = n0m + tid;
        int nt = blockIdx.y;
        size_t sidx = (size_t)v * NT + nt;
        g_tmin[sidx] = funflip(s_min[tid]);
        int c = s_cnt[tid];
        g_tcnt[sidx] = c;
        int cw = c < TCAP ? c : TCAP;
        for (int e = 0; e < cw; ++e) {
            g_tck[sidx * TCAP + e] = s_ck[tid * TCAP + e];
            g_tcs[sidx * TCAP + e] = s_cs[tid * TCAP + e];
        }
    }
}

// ---------------------------------------------------------------------------
// Merge: per vector, reduce 16 tile summaries -> final candidates.
__global__ __launch_bounds__(256)
void k_merge() {
    int v = blockIdx.x * blockDim.x + threadIdx.x;
    if (v >= NN) return;
    size_t base = (size_t)v * NT;

    float fmin = 3.4e38f;
#pragma unroll
    for (int nt = 0; nt < NT; ++nt)
        fmin = fminf(fmin, g_tmin[base + nt]);
    float thr = fmin + MARGIN;

    int cnt = 0;
    bool ovf = false;
#pragma unroll
    for (int nt = 0; nt < NT; ++nt) {
        float tm = g_tmin[base + nt];
        int c = g_tcnt[base + nt];
        if (c > TCAP) {
            if (tm <= thr) ovf = true;   // dropped entry might qualify
            c = TCAP;
        }
        for (int e = 0; e < c; ++e) {
            if (g_tcs[(base + nt) * TCAP + e] <= thr) {
                if (cnt < CAP) g_cand[v * CAP + cnt] = g_tck[(base + nt) * TCAP + e];
                ++cnt;
            }
        }
    }
    if (ovf) cnt = KK;    // force full exact scan fallback
    g_cnt[v] = cnt;
}

// ---------------------------------------------------------------------------
// Exact argmin, warp-per-vector (bitwise-proven fp32 chains; tie -> lowest k).
__global__ __launch_bounds__(256)
void k_exact(const float* __restrict__ res, const float* __restrict__ cbq,
             int q, float* __restrict__ out) {
    int v = blockIdx.x * 8 + (threadIdx.x >> 5);
    int lane = threadIdx.x & 31;
    if (v >= NN) return;
    int b = v / TT, t = v - b * TT;
    int cnt = g_cnt[v];
    int bi;
    if (cnt == 1) {
        bi = g_cand[v * CAP];
    } else {
        const float* xp = res + (size_t)b * (DIMD * TT) + t;
        float sx = g_sx[v];
        const float* scq = g_sc + q * KK;
        float bd = 3.4e38f;
        int   bk = KK;
        if (cnt <= CAP) {
            if (lane < cnt) {
                int k = g_cand[v * CAP + lane];
                const float* crow = cbq + (size_t)k * DIMD;
                float dot = 0.f;
                for (int d = 0; d < DIMD; ++d)
                    dot = __fmaf_rn(xp[(size_t)d * TT], crow[d], dot);
                bd = __fadd_rn(__fadd_rn(sx, -__fmul_rn(2.0f, dot)), scq[k]);
                bk = k;
            }
        } else {
            for (int k = lane; k < KK; k += 32) {
                const float* crow = cbq + (size_t)k * DIMD;
                float dot = 0.f;
                for (int d = 0; d < DIMD; ++d)
                    dot = __fmaf_rn(xp[(size_t)d * TT], crow[d], dot);
                float dist = __fadd_rn(__fadd_rn(sx, -__fmul_rn(2.0f, dot)),
                                       scq[k]);
                if (dist < bd) { bd = dist; bk = k; }
            }
        }
#pragma unroll
        for (int o = 16; o > 0; o >>= 1) {
            float od = __shfl_xor_sync(0xFFFFFFFFu, bd, o);
            int   ok = __shfl_xor_sync(0xFFFFFFFFu, bk, o);
            if (od < bd || (od == bd && ok < bk)) { bd = od; bk = ok; }
        }
        bi = bk;
    }
    if (lane == 0) {
        g_idx[v] = bi;
        out[IDX_OFF + (size_t)b * (NQ * TT) + (size_t)q * TT + t] = (float)bi;
    }
}

// ---------------------------------------------------------------------------
// Update kernel (bitwise-proven): straight-through quantize, output accum,
// residual update, per-block loss partial.
__global__ __launch_bounds__(256)
void k_update(const float* __restrict__ res_in, const float* __restrict__ cbq,
              int q, float* __restrict__ out) {
    int tid = threadIdx.x;
    int nl = tid & 63, dc = tid >> 6;
    int n = blockIdx.x * 64 + nl;
    int b = n / TT, t = n - b * TT;
    int k = g_idx[n];
    const float* crow = cbq + (size_t)k * DIMD;
    size_t base = (size_t)b * (DIMD * TT) + t;

    double lacc = 0.0;
    int d0 = dc * 128;
    for (int d = d0; d < d0 + 128; ++d) {
        size_t off = base + (size_t)d * TT;
        float r = res_in[off];
        float c = crow[d];
        float t1 = __fadd_rn(c, -r);
        float qo = __fadd_rn(r, t1);
        float qprev = (q == 0) ? 0.f : out[off];
        out[off]   = __fadd_rn(qprev, qo);
        g_res[off] = __fadd_rn(r, -qo);
        lacc += (double)t1 * (double)t1;
    }

    __shared__ double sred[256];
    sred[tid] = lacc;
    __syncthreads();
    for (int s = 128; s > 0; s >>= 1) {
        if (tid < s) sred[tid] += sred[tid + s];
        __syncthreads();
    }
    if (tid == 0) g_partial[q * UPD_BLOCKS + blockIdx.x] = sred[0];
}

__global__ void k_final(float* __restrict__ out) {
    __shared__ float lq[NQ];
    int q = threadIdx.x;
    if (q < NQ) {
        double s = 0.0;
        for (int i = 0; i < UPD_BLOCKS; ++i) s += g_partial[q * UPD_BLOCKS + i];
        lq[q] = (float)(s / (double)QOUT_ELEMS);
    }
    __syncthreads();
    if (q == 0) {
        float tl = 0.f;
        for (int i = 0; i < NQ; ++i) tl = __fadd_rn(tl, lq[i]);
        out[LOSS_OFF] = tl;
    }
}

// ---------------------------------------------------------------------------
extern "C" void kernel_launch(void* const* d_in, const int* in_sizes, int n_in,
                              void* d_out, int out_size) {
    const float* x  = (const float*)d_in[0];
    const float* cb = (const float*)d_in[1];
    float* out = (float*)d_out;

    void* resg_v = nullptr;
    cudaGetSymbolAddress(&resg_v, g_res);
    const float* resg = (const float*)resg_v;

    cudaFuncSetAttribute(k_gemm, cudaFuncAttributeMaxDynamicSharedMemorySize,
                         GEMM_SMEM);

    k_sc<<<(NQ * KK + 255) / 256, 256>>>(cb);
    k_cbb<<<(int)(((size_t)NQ * KK * DIMD + 255) / 256), 256>>>(cb);

    const float* res = x;   // stage 0 reads x directly
    for (int q = 0; q < NQ; ++q) {
        const float* cbq = cb + (size_t)q * KK * DIMD;
        k_sx_xb<<<(NN + 255) / 256, 256>>>(res);
        dim3 gg(MT, NT);
        k_gemm<<<gg, 256, GEMM_SMEM>>>(q);
        k_merge<<<(NN + 255) / 256, 256>>>();
        k_exact<<<NN / 8, 256>>>(res, cbq, q, out);
        k_update<<<UPD_BLOCKS, 256>>>(res, cbq, q, out);
        res = resg;
    }
    k_final<<<1, 32>>>(out);
}